// round 14
// baseline (speedup 1.0000x reference)
#include <cuda_runtime.h>
#include <cuda_fp16.h>
#include <cstdint>

#define NNODES 20000
#define NEDGES 160000
#define BBATCH 64
#define FTEXT  300
#define FHID   1024
#define FOUT   1664
#define NEG_SLOPE 0.2f
#define NSPLIT 13          // T1 split-K factor (13 * 128 = 1664)
#define G1_GRID (16 * 157) // GEMM1 CTAs

// ---------------- scratch (zero-initialized at load; re-zeroed each run) -----
__device__ float g_deg[NNODES];
__device__ float g_dinv[NNODES];
__device__ int   g_cnt[NNODES];
__device__ int   g_rowptr[NNODES + 1];
__device__ int   g_cursor[NNODES];
__device__ int   g_colsrc[NEDGES];    // pre-scaled: src * FTEXT
__device__ int   g_colsrcB[NEDGES];   // pre-scaled: src * BBATCH
__device__ float g_colw[NEDGES];
__device__ float g_Y[(size_t)NNODES * FTEXT];
__device__ float g_X1[(size_t)NNODES * FHID];
__device__ float g_W1t[(size_t)FHID * FTEXT];
__device__ float g_T1p[(size_t)NSPLIT * BBATCH * FHID];
__device__ float g_T1[BBATCH * FHID];
__device__ float g_T2[(size_t)NNODES * BBATCH];
__device__ float g_imgb2[BBATCH];

// ---------------- PTX helpers (sm_80+ baseline only) ----------------
__device__ __forceinline__ uint32_t smem_to_u32(const void* p) {
    uint32_t a;
    asm("{ .reg .u64 t; cvta.to.shared.u64 t, %1; cvt.u32.u64 %0, t; }" : "=r"(a) : "l"(p));
    return a;
}
__device__ __forceinline__ void ldsm_x4(uint32_t* r, uint32_t addr) {
    asm volatile("ldmatrix.sync.aligned.m8n8.x4.shared.b16 {%0,%1,%2,%3}, [%4];"
        : "=r"(r[0]), "=r"(r[1]), "=r"(r[2]), "=r"(r[3]) : "r"(addr));
}
__device__ __forceinline__ void mma_f16(float* c, const uint32_t* a, const uint32_t* b) {
    asm volatile(
        "mma.sync.aligned.m16n8k16.row.col.f32.f16.f16.f32 "
        "{%0,%1,%2,%3}, {%4,%5,%6,%7}, {%8,%9}, {%0,%1,%2,%3};"
        : "+f"(c[0]), "+f"(c[1]), "+f"(c[2]), "+f"(c[3])
        : "r"(a[0]), "r"(a[1]), "r"(a[2]), "r"(a[3]), "r"(b[0]), "r"(b[1]));
}
__device__ __forceinline__ uint2 f4_h(float4 v) {
    __half2 h01(__float2half_rn(v.x), __float2half_rn(v.y));
    __half2 h23(__float2half_rn(v.z), __float2half_rn(v.w));
    uint2 h;
    h.x = *(uint32_t*)&h01; h.y = *(uint32_t*)&h23;
    return h;
}

// ---------------- launch 0: degree atomics + W1 transpose (independent) ------
__global__ void k_deg_w1t(const int* __restrict__ dst, const float* __restrict__ w,
                          const float* __restrict__ W1) {
    int tid = threadIdx.x;
    if (blockIdx.x < 625) {
        int e = blockIdx.x * 256 + tid;
        if (e < NEDGES) {
            int d = dst[e];
            atomicAdd(&g_deg[d], w[e]);
            atomicAdd(&g_cnt[d], 1);
        }
    } else {
        __shared__ float s[32][33];
        int bidx = blockIdx.x - 625;
        int n0 = (bidx & 31) * 32;
        int k0 = (bidx >> 5) * 32;
        int tx = tid & 31, ty = tid >> 5;
        #pragma unroll
        for (int i = 0; i < 32; i += 8) {
            int k = k0 + ty + i, n = n0 + tx;
            if (k < FTEXT) s[ty + i][tx] = W1[(size_t)k * FHID + n];
        }
        __syncthreads();
        #pragma unroll
        for (int i = 0; i < 32; i += 8) {
            int n = n0 + ty + i, k = k0 + tx;
            if (k < FTEXT) g_W1t[(size_t)n * FTEXT + k] = s[tx][ty + i];
        }
    }
}

// ---------------- launch 1: warp-shuffle scan + dinv ----------------
__global__ void k_scandinv() {
    const int CH = 20;
    __shared__ int wtot[32];
    __shared__ int s_total;
    int t = threadIdx.x;
    int lane = t & 31, wid = t >> 5;
    int base = t * CH;
    int loc[CH];
    int sum = 0;
    #pragma unroll
    for (int i = 0; i < CH; i++) {
        int idx = base + i;
        int v = 0;
        if (idx < NNODES) {
            v = g_cnt[idx];
            float d = g_deg[idx];
            g_dinv[idx] = (d > 0.f) ? rsqrtf(d) : 0.f;
        }
        loc[i] = sum;
        sum += v;
    }
    int inc = sum;
    #pragma unroll
    for (int off = 1; off < 32; off <<= 1) {
        int v = __shfl_up_sync(0xffffffffu, inc, off);
        if (lane >= off) inc += v;
    }
    if (lane == 31) wtot[wid] = inc;
    __syncthreads();
    if (wid == 0) {
        int v = wtot[lane];
        int wi = v;
        #pragma unroll
        for (int off = 1; off < 32; off <<= 1) {
            int u = __shfl_up_sync(0xffffffffu, wi, off);
            if (lane >= off) wi += u;
        }
        wtot[lane] = wi - v;
        if (lane == 31) s_total = wi;
    }
    __syncthreads();
    int off0 = wtot[wid] + inc - sum;
    #pragma unroll
    for (int i = 0; i < CH; i++) {
        int idx = base + i;
        if (idx < NNODES) g_rowptr[idx] = off0 + loc[i];
    }
    if (t == 0) g_rowptr[NNODES] = s_total;
}

// ---------------- launch 2: fill CSR (pre-scaled indices) + T1 split-K -------
__global__ void __launch_bounds__(256) k_fill_t1(
    const int* __restrict__ src, const int* __restrict__ dst,
    const float* __restrict__ w,
    const float* __restrict__ img, const float* __restrict__ W2)
{
    __shared__ float As[16][64 + 1];
    __shared__ float Bs[16][64 + 1];
    int tid = threadIdx.x;
    if (blockIdx.x < 625) {
        int e = blockIdx.x * 256 + tid;
        if (e < NEDGES) {
            int s = src[e], d = dst[e];
            float nm = g_dinv[s] * w[e] * g_dinv[d];
            int pos = g_rowptr[d] + atomicAdd(&g_cursor[d], 1);
            g_colsrc[pos]  = s * FTEXT;
            g_colsrcB[pos] = s * BBATCH;
            g_colw[pos]    = nm;
        }
    } else {
        int bidx = blockIdx.x - 625;          // 0..207
        int col0 = (bidx & 15) * 64;
        int sk = bidx >> 4;
        int kbase = sk * 128;
        const int BK = 16;
        int tx = tid & 15, ty = tid >> 4;
        float acc[4][4] = {};
        int r = tid >> 2, kq = (tid & 3) * 4;
        for (int t0 = 0; t0 < 128; t0 += BK) {
            float4 av = *(const float4*)(img + (size_t)r * FOUT + kbase + t0 + kq);
            As[kq + 0][r] = av.x; As[kq + 1][r] = av.y;
            As[kq + 2][r] = av.z; As[kq + 3][r] = av.w;
            float4 bv = *(const float4*)(W2 + (size_t)(col0 + r) * FOUT + kbase + t0 + kq);
            Bs[kq + 0][r] = bv.x; Bs[kq + 1][r] = bv.y;
            Bs[kq + 2][r] = bv.z; Bs[kq + 3][r] = bv.w;
            __syncthreads();
            #pragma unroll
            for (int k = 0; k < BK; k++) {
                float a[4], b[4];
                #pragma unroll
                for (int i = 0; i < 4; i++) a[i] = As[k][ty * 4 + i];
                #pragma unroll
                for (int j = 0; j < 4; j++) b[j] = Bs[k][tx * 4 + j];
                #pragma unroll
                for (int i = 0; i < 4; i++)
                    #pragma unroll
                    for (int j = 0; j < 4; j++)
                        acc[i][j] += a[i] * b[j];
            }
            __syncthreads();
        }
        float* cp = g_T1p + (size_t)sk * (BBATCH * FHID);
        #pragma unroll
        for (int i = 0; i < 4; i++) {
            int b = ty * 4 + i;
            #pragma unroll
            for (int j = 0; j < 4; j++)
                cp[(size_t)b * FHID + col0 + tx * 4 + j] = acc[i][j];
        }
    }
}

// ---------------- launch 3: Y = A @ X, float4 gather (75 lanes), unroll x2 ---
__global__ void k_aggY(const float* __restrict__ X) {
    __shared__ int   ss[128];
    __shared__ float sw[128];
    int n = blockIdx.x;
    int tid = threadIdx.x;
    int st = g_rowptr[n], en = g_rowptr[n + 1];
    float4 acc = make_float4(0.f, 0.f, 0.f, 0.f);
    bool act = (tid < 75);          // 75 * 4 = 300
    for (int e0 = st; e0 < en; e0 += 128) {
        int ne = min(128, en - e0);
        if (tid < ne) { ss[tid] = g_colsrc[e0 + tid]; sw[tid] = g_colw[e0 + tid]; }
        __syncthreads();
        if (act) {
            int j = 0;
            for (; j + 2 <= ne; j += 2) {
                const float4* x0 = (const float4*)(X + ss[j]);
                const float4* x1 = (const float4*)(X + ss[j + 1]);
                float w0 = sw[j], w1 = sw[j + 1];
                float4 p = x0[tid];
                float4 q = x1[tid];
                acc.x += w0 * p.x + w1 * q.x;
                acc.y += w0 * p.y + w1 * q.y;
                acc.z += w0 * p.z + w1 * q.z;
                acc.w += w0 * p.w + w1 * q.w;
            }
            if (j < ne) {
                const float4* x0 = (const float4*)(X + ss[j]);
                float w0 = sw[j];
                float4 p = x0[tid];
                acc.x += w0 * p.x;
                acc.y += w0 * p.y;
                acc.z += w0 * p.z;
                acc.w += w0 * p.w;
            }
        }
        __syncthreads();
    }
    if (act) ((float4*)(g_Y + (size_t)n * FTEXT))[tid] = acc;
}

// ---------------- plain-fp16 GEMM core, 128x64 CTA tile, 256 threads ---------
template<bool BIAS, bool LEAKY>
__device__ __forceinline__ void gemm_core(
    const float* __restrict__ A, int lda,
    const float* __restrict__ B, int ldb,
    float* __restrict__ C, int ldc,
    const float* __restrict__ bias,
    int M, int N, int K, int bx, int by, char* smem)
{
    const int A_BYTES = 128 * 80;
    const int B_BYTES = 64 * 80;
    const int STAGE   = A_BYTES + B_BYTES;   // 15360

    int tid  = threadIdx.x;
    int wid  = tid >> 5, lane = tid & 31;
    int wm   = wid & 3, wn = wid >> 2;
    int row0 = by * 128;
    int col0 = bx * 64;
    uint32_t smem_u = smem_to_u32(smem);

    float acc[2][4][4];
    #pragma unroll
    for (int mt = 0; mt < 2; mt++)
        #pragma unroll
        for (int nt = 0; nt < 4; nt++)
            #pragma unroll
            for (int q = 0; q < 4; q++) acc[mt][nt][q] = 0.f;

    float4 aR[4], bR[2];
    const int nT = (K + 31) >> 5;

    auto LDG = [&](int t) {
        int kb = t * 32;
        #pragma unroll
        for (int i = 0; i < 4; i++) {
            int idx = tid + i * 256;
            int r = idx >> 3, kk = (idx & 7) * 4;
            int row = row0 + r, kg = kb + kk;
            float4 v = make_float4(0.f, 0.f, 0.f, 0.f);
            if (row < M && kg < K) v = *(const float4*)(A + (size_t)row * lda + kg);
            aR[i] = v;
        }
        #pragma unroll
        for (int i = 0; i < 2; i++) {
            int idx = tid + i * 256;
            int c = idx >> 3, kk = (idx & 7) * 4;
            int col = col0 + c, kg = kb + kk;
            float4 v = make_float4(0.f, 0.f, 0.f, 0.f);
            if (col < N && kg < K) v = *(const float4*)(B + (size_t)col * ldb + kg);
            bR[i] = v;
        }
    };
    auto STS = [&](int s) {
        char* base = smem + s * STAGE;
        #pragma unroll
        for (int i = 0; i < 4; i++) {
            int idx = tid + i * 256;
            int r = idx >> 3, kk = (idx & 7) * 4;
            *(uint2*)(base + r * 80 + kk * 2) = f4_h(aR[i]);
        }
        #pragma unroll
        for (int i = 0; i < 2; i++) {
            int idx = tid + i * 256;
            int c = idx >> 3, kk = (idx & 7) * 4;
            *(uint2*)(base + A_BYTES + c * 80 + kk * 2) = f4_h(bR[i]);
        }
    };
    auto COMPUTE = [&](int s) {
        uint32_t sb = smem_u + s * STAGE;
        uint32_t aH = sb + (uint32_t)((wm * 32 + (lane & 15)) * 80 + (lane >> 4) * 16);
        uint32_t bH = sb + A_BYTES +
            (uint32_t)((wn * 32 + ((lane >> 4) & 1) * 8 + (lane & 7)) * 80 + ((lane >> 3) & 1) * 16);
        #pragma unroll
        for (int ks = 0; ks < 2; ks++) {
            uint32_t ah[2][4], bh[2][4];
            #pragma unroll
            for (int mt = 0; mt < 2; mt++)
                ldsm_x4(ah[mt], aH + mt * 16 * 80 + ks * 32);
            #pragma unroll
            for (int g = 0; g < 2; g++)
                ldsm_x4(bh[g], bH + g * 16 * 80 + ks * 32);
            #pragma unroll
            for (int mt = 0; mt < 2; mt++)
                #pragma unroll
                for (int nt = 0; nt < 4; nt++)
                    mma_f16(acc[mt][nt], ah[mt], &bh[nt >> 1][(nt & 1) * 2]);
        }
    };

    LDG(0);
    STS(0);
    if (nT > 1) LDG(1);
    __syncthreads();
    for (int t = 0; t < nT; t++) {
        COMPUTE(t & 1);
        if (t + 1 < nT) STS((t + 1) & 1);
        __syncthreads();
        if (t + 2 < nT) LDG(t + 2);
    }

    int rw = row0 + wm * 32;
    int cw = col0 + wn * 32;
    #pragma unroll
    for (int mt = 0; mt < 2; mt++) {
        #pragma unroll
        for (int half = 0; half < 2; half++) {
            int row = rw + mt * 16 + (lane >> 2) + half * 8;
            if (row >= M) continue;
            #pragma unroll
            for (int nt = 0; nt < 4; nt++) {
                int col = cw + nt * 8 + (lane & 3) * 2;
                if (col >= N) continue;
                float v0 = acc[mt][nt][half * 2 + 0];
                float v1 = acc[mt][nt][half * 2 + 1];
                if (BIAS) { v0 += bias[col]; v1 += bias[col + 1]; }
                if (LEAKY) {
                    v0 = (v0 >= 0.f) ? v0 : NEG_SLOPE * v0;
                    v1 = (v1 >= 0.f) ? v1 : NEG_SLOPE * v1;
                }
                float2 o; o.x = v0; o.y = v1;
                *(float2*)(C + (size_t)row * ldc + col) = o;
            }
        }
    }
}

// ---------------- launch 4: GEMM1 + T1 reduce + imgb2 (merged) ---------------
__global__ void __launch_bounds__(256, 2) k_gemm1_fused(
    const float* __restrict__ A, const float* __restrict__ B,
    float* __restrict__ C, const float* __restrict__ bias,
    const float* __restrict__ img, const float* __restrict__ b2)
{
    extern __shared__ char smem[];
    if (blockIdx.x < G1_GRID) {
        int bx = blockIdx.x & 15;
        int by = blockIdx.x >> 4;
        gemm_core<true, true>(A, FTEXT, B, FTEXT, C, FHID, bias,
                              NNODES, FHID, FTEXT, bx, by, smem);
    } else if (blockIdx.x < G1_GRID + 256) {
        int idx = (blockIdx.x - G1_GRID) * 256 + threadIdx.x;
        float acc = 0.f;
        #pragma unroll
        for (int s = 0; s < NSPLIT; s++)
            acc += g_T1p[(size_t)s * (BBATCH * FHID) + idx];
        g_T1[idx] = acc;
    } else {
        int wid = threadIdx.x >> 5, lane = threadIdx.x & 31;
        for (int i = 0; i < 8; i++) {
            int b = wid * 8 + i;
            float acc = 0.f;
            for (int k = lane; k < FOUT; k += 32)
                acc += img[(size_t)b * FOUT + k] * b2[k];
            #pragma unroll
            for (int off = 16; off > 0; off >>= 1)
                acc += __shfl_down_sync(0xffffffffu, acc, off);
            if (lane == 0) g_imgb2[b] = acc;
        }
    }
}

// ---------------- launch 5: T2 = X1 @ T1^T, 64-row tiles, plain fp16 ---------
__global__ void __launch_bounds__(128, 4) k_t2(
    const float* __restrict__ A, const float* __restrict__ B,
    float* __restrict__ C)
{
    extern __shared__ char smem[];
    const int A64 = 64 * 80;
    const int B64 = 64 * 80;
    const int STAGE = A64 + B64;           // 10240
    const int M = NNODES, K = FHID;

    int tid = threadIdx.x;
    int wid = tid >> 5, lane = tid & 31;
    int wm = wid & 1, wn = wid >> 1;
    int row0 = blockIdx.x * 64;
    uint32_t smem_u = smem_to_u32(smem);

    float acc[2][4][4];
    #pragma unroll
    for (int mt = 0; mt < 2; mt++)
        #pragma unroll
        for (int nt = 0; nt < 4; nt++)
            #pragma unroll
            for (int q = 0; q < 4; q++) acc[mt][nt][q] = 0.f;

    float4 aR[4], bR[4];
    const int nT = K >> 5;

    auto LDG = [&](int t) {
        int kb = t * 32;
        #pragma unroll
        for (int i = 0; i < 4; i++) {
            int idx = tid + i * 128;
            int r = idx >> 3, kk = (idx & 7) * 4;
            int row = row0 + r; row = (row < M) ? row : (M - 1);
            aR[i] = *(const float4*)(A + (size_t)row * K + kb + kk);
            bR[i] = *(const float4*)(B + (size_t)r * K + kb + kk);
        }
    };
    auto STS = [&](int s) {
        char* base = smem + s * STAGE;
        #pragma unroll
        for (int i = 0; i < 4; i++) {
            int idx = tid + i * 128;
            int r = idx >> 3, kk = (idx & 7) * 4;
            *(uint2*)(base + r * 80 + kk * 2) = f4_h(aR[i]);
            *(uint2*)(base + A64 + r * 80 + kk * 2) = f4_h(bR[i]);
        }
    };
    auto COMPUTE = [&](int s) {
        uint32_t sb = smem_u + s * STAGE;
        uint32_t aH = sb + (uint32_t)((wm * 32 + (lane & 15)) * 80 + (lane >> 4) * 16);
        uint32_t bH = sb + A64 +
            (uint32_t)((wn * 32 + ((lane >> 4) & 1) * 8 + (lane & 7)) * 80 + ((lane >> 3) & 1) * 16);
        #pragma unroll
        for (int ks = 0; ks < 2; ks++) {
            uint32_t ah[2][4], bh[2][4];
            #pragma unroll
            for (int mt = 0; mt < 2; mt++)
                ldsm_x4(ah[mt], aH + mt * 16 * 80 + ks * 32);
            #pragma unroll
            for (int g = 0; g < 2; g++)
                ldsm_x4(bh[g], bH + g * 16 * 80 + ks * 32);
            #pragma unroll
            for (int mt = 0; mt < 2; mt++)
                #pragma unroll
                for (int nt = 0; nt < 4; nt++)
                    mma_f16(acc[mt][nt], ah[mt], &bh[nt >> 1][(nt & 1) * 2]);
        }
    };

    LDG(0);
    STS(0);
    LDG(1);
    __syncthreads();
    for (int t = 0; t < nT; t++) {
        COMPUTE(t & 1);
        if (t + 1 < nT) STS((t + 1) & 1);
        __syncthreads();
        if (t + 2 < nT) LDG(t + 2);
    }

    int rw = row0 + wm * 32;
    int cw = wn * 32;
    #pragma unroll
    for (int mt = 0; mt < 2; mt++) {
        #pragma unroll
        for (int half = 0; half < 2; half++) {
            int row = rw + mt * 16 + (lane >> 2) + half * 8;
            if (row >= M) continue;
            #pragma unroll
            for (int nt = 0; nt < 4; nt++) {
                int col = cw + nt * 8 + (lane & 3) * 2;
                float2 o;
                o.x = acc[mt][nt][half * 2 + 0];
                o.y = acc[mt][nt][half * 2 + 1];
                *(float2*)(C + (size_t)row * BBATCH + col) = o;
            }
        }
    }
}

// ---------------- launch 6: output agg (float2/lane, warp-sync) + transpose --
__global__ void __launch_bounds__(256) k_aggOutT(float* __restrict__ out) {
    if (blockIdx.x >= 625) {
        int i = (blockIdx.x - 625) * 256 + threadIdx.x;
        if (i < NNODES) { g_deg[i] = 0.f; g_cnt[i] = 0; g_cursor[i] = 0; }
        return;
    }
    __shared__ float s[32][65];
    int n0 = blockIdx.x * 32;
    int tid = threadIdx.x;
    int slot = tid >> 5;                 // 0..7 (one warp per slot)
    int b2 = tid & 31;                   // float2 lane: cols 2*b2, 2*b2+1
    float bx = g_imgb2[2 * b2];
    float by = g_imgb2[2 * b2 + 1];
    #pragma unroll
    for (int rnd = 0; rnd < 4; rnd++) {
        int nl = rnd * 8 + slot;
        int n = n0 + nl;
        float ax = bx, ay = by;
        int st = g_rowptr[n], en = g_rowptr[n + 1];
        for (int e = st; e < en; e++) {
            float w = g_colw[e];
            float2 v = *(const float2*)(g_T2 + g_colsrcB[e] + 2 * b2);
            ax += w * v.x;
            ay += w * v.y;
        }
        s[nl][2 * b2]     = ax;
        s[nl][2 * b2 + 1] = ay;
    }
    __syncthreads();
    #pragma unroll
    for (int i = 0; i < 8; i++) {
        int idx = tid + i * 256;
        int bb = idx >> 5, nn = idx & 31;
        out[(size_t)bb * NNODES + n0 + nn] = s[nn][bb];
    }
}

// ---------------- launch ----------------
extern "C" void kernel_launch(void* const* d_in, const int* in_sizes, int n_in,
                              void* d_out, int out_size) {
    const float* img  = (const float*)d_in[0];
    const float* nf   = (const float*)d_in[1];
    const int*   esrc = (const int*)d_in[2];
    const int*   edst = (const int*)d_in[3];
    const float* ew   = (const float*)d_in[4];
    const float* W1   = (const float*)d_in[5];
    const float* b1   = (const float*)d_in[6];
    const float* W2   = (const float*)d_in[7];
    const float* b2   = (const float*)d_in[8];
    float* out = (float*)d_out;

    float *dY, *dX1, *dW1t, *dT1, *dT2;
    cudaGetSymbolAddress((void**)&dY,   g_Y);
    cudaGetSymbolAddress((void**)&dX1,  g_X1);
    cudaGetSymbolAddress((void**)&dW1t, g_W1t);
    cudaGetSymbolAddress((void**)&dT1,  g_T1);
    cudaGetSymbolAddress((void**)&dT2,  g_T2);

    const int SMEM1 = 30720;   // gemm_core: 2 stages x 15360
    const int SMEM2 = 20480;   // k_t2:      2 stages x 10240
    cudaFuncSetAttribute(k_gemm1_fused, cudaFuncAttributeMaxDynamicSharedMemorySize, SMEM1);
    cudaFuncSetAttribute(k_t2,          cudaFuncAttributeMaxDynamicSharedMemorySize, SMEM2);

    // 0: degree atomics + W1 transpose
    k_deg_w1t<<<625 + 320, 256>>>(edst, ew, W1);
    // 1: scan + dinv
    k_scandinv<<<1, 1024>>>();
    // 2: CSR fill (pre-scaled indices) + T1 split-K
    k_fill_t1<<<625 + 16 * NSPLIT, 256>>>(esrc, edst, ew, img, W2);
    // 3: layer-1 aggregation (float4 gather)
    k_aggY<<<NNODES, 128>>>(nf);
    // 4: GEMM1 + T1 reduce + imgb2 (plain fp16 MMA)
    k_gemm1_fused<<<G1_GRID + 256 + 1, 256, SMEM1>>>(dY, dW1t, dX1, b1, img, b2);
    // 5: T2 (plain fp16 MMA, 64-row tiles)
    k_t2<<<(NNODES + 63) / 64, 128, SMEM2>>>(dX1, dT1, dT2);
    // 6: output aggregation (float2/lane) + transpose + re-zero scratch
    k_aggOutT<<<625 + 79, 256>>>(out);
}

// round 15
// speedup vs baseline: 1.0167x; 1.0167x over previous
#include <cuda_runtime.h>
#include <cuda_fp16.h>
#include <cstdint>

#define NNODES 20000
#define NEDGES 160000
#define BBATCH 64
#define FTEXT  300
#define FHID   1024
#define FOUT   1664
#define NEG_SLOPE 0.2f
#define NSPLIT 13          // T1 split-K factor (13 * 128 = 1664)
#define G1_GRID (16 * 157) // GEMM1 CTAs

// ---------------- scratch (zero-initialized at load; re-zeroed each run) -----
__device__ float g_deg[NNODES];
__device__ float g_dinv[NNODES];
__device__ int   g_cnt[NNODES];
__device__ int   g_rowptr[NNODES + 1];
__device__ int   g_cursor[NNODES];
__device__ int   g_colsrc[NEDGES];    // pre-scaled: src * FTEXT
__device__ int   g_colsrcB[NEDGES];   // pre-scaled: src * BBATCH
__device__ float g_colw[NEDGES];
__device__ float g_Y[(size_t)NNODES * FTEXT];
__device__ float g_X1[(size_t)NNODES * FHID];
__device__ float g_W1t[(size_t)FHID * FTEXT];
__device__ float g_T1p[(size_t)NSPLIT * BBATCH * FHID];
__device__ float g_T1[BBATCH * FHID];
__device__ float g_T2[(size_t)NNODES * BBATCH];
__device__ float g_imgb2[BBATCH];

// ---------------- PTX helpers (sm_80+ baseline only) ----------------
__device__ __forceinline__ uint32_t smem_to_u32(const void* p) {
    uint32_t a;
    asm("{ .reg .u64 t; cvta.to.shared.u64 t, %1; cvt.u32.u64 %0, t; }" : "=r"(a) : "l"(p));
    return a;
}
__device__ __forceinline__ void ldsm_x4(uint32_t* r, uint32_t addr) {
    asm volatile("ldmatrix.sync.aligned.m8n8.x4.shared.b16 {%0,%1,%2,%3}, [%4];"
        : "=r"(r[0]), "=r"(r[1]), "=r"(r[2]), "=r"(r[3]) : "r"(addr));
}
__device__ __forceinline__ void mma_f16(float* c, const uint32_t* a, const uint32_t* b) {
    asm volatile(
        "mma.sync.aligned.m16n8k16.row.col.f32.f16.f16.f32 "
        "{%0,%1,%2,%3}, {%4,%5,%6,%7}, {%8,%9}, {%0,%1,%2,%3};"
        : "+f"(c[0]), "+f"(c[1]), "+f"(c[2]), "+f"(c[3])
        : "r"(a[0]), "r"(a[1]), "r"(a[2]), "r"(a[3]), "r"(b[0]), "r"(b[1]));
}
__device__ __forceinline__ uint2 f4_h(float4 v) {
    __half2 h01(__float2half_rn(v.x), __float2half_rn(v.y));
    __half2 h23(__float2half_rn(v.z), __float2half_rn(v.w));
    uint2 h;
    h.x = *(uint32_t*)&h01; h.y = *(uint32_t*)&h23;
    return h;
}

// ---------------- launch 0: degree atomics + W1 transpose (independent) ------
__global__ void k_deg_w1t(const int* __restrict__ dst, const float* __restrict__ w,
                          const float* __restrict__ W1) {
    int tid = threadIdx.x;
    if (blockIdx.x < 625) {
        int e = blockIdx.x * 256 + tid;
        if (e < NEDGES) {
            int d = dst[e];
            atomicAdd(&g_deg[d], w[e]);
            atomicAdd(&g_cnt[d], 1);
        }
    } else {
        __shared__ float s[32][33];
        int bidx = blockIdx.x - 625;
        int n0 = (bidx & 31) * 32;
        int k0 = (bidx >> 5) * 32;
        int tx = tid & 31, ty = tid >> 5;
        #pragma unroll
        for (int i = 0; i < 32; i += 8) {
            int k = k0 + ty + i, n = n0 + tx;
            if (k < FTEXT) s[ty + i][tx] = W1[(size_t)k * FHID + n];
        }
        __syncthreads();
        #pragma unroll
        for (int i = 0; i < 32; i += 8) {
            int n = n0 + ty + i, k = k0 + tx;
            if (k < FTEXT) g_W1t[(size_t)n * FTEXT + k] = s[tx][ty + i];
        }
    }
}

// ---------------- launch 1: warp-shuffle scan + dinv ----------------
__global__ void k_scandinv() {
    const int CH = 20;
    __shared__ int wtot[32];
    __shared__ int s_total;
    int t = threadIdx.x;
    int lane = t & 31, wid = t >> 5;
    int base = t * CH;
    int loc[CH];
    int sum = 0;
    #pragma unroll
    for (int i = 0; i < CH; i++) {
        int idx = base + i;
        int v = 0;
        if (idx < NNODES) {
            v = g_cnt[idx];
            float d = g_deg[idx];
            g_dinv[idx] = (d > 0.f) ? rsqrtf(d) : 0.f;
        }
        loc[i] = sum;
        sum += v;
    }
    int inc = sum;
    #pragma unroll
    for (int off = 1; off < 32; off <<= 1) {
        int v = __shfl_up_sync(0xffffffffu, inc, off);
        if (lane >= off) inc += v;
    }
    if (lane == 31) wtot[wid] = inc;
    __syncthreads();
    if (wid == 0) {
        int v = wtot[lane];
        int wi = v;
        #pragma unroll
        for (int off = 1; off < 32; off <<= 1) {
            int u = __shfl_up_sync(0xffffffffu, wi, off);
            if (lane >= off) wi += u;
        }
        wtot[lane] = wi - v;
        if (lane == 31) s_total = wi;
    }
    __syncthreads();
    int off0 = wtot[wid] + inc - sum;
    #pragma unroll
    for (int i = 0; i < CH; i++) {
        int idx = base + i;
        if (idx < NNODES) g_rowptr[idx] = off0 + loc[i];
    }
    if (t == 0) g_rowptr[NNODES] = s_total;
}

// ---------------- launch 2: fill CSR (pre-scaled indices) + T1 split-K -------
__global__ void __launch_bounds__(256) k_fill_t1(
    const int* __restrict__ src, const int* __restrict__ dst,
    const float* __restrict__ w,
    const float* __restrict__ img, const float* __restrict__ W2)
{
    __shared__ float As[16][64 + 1];
    __shared__ float Bs[16][64 + 1];
    int tid = threadIdx.x;
    if (blockIdx.x < 625) {
        int e = blockIdx.x * 256 + tid;
        if (e < NEDGES) {
            int s = src[e], d = dst[e];
            float nm = g_dinv[s] * w[e] * g_dinv[d];
            int pos = g_rowptr[d] + atomicAdd(&g_cursor[d], 1);
            g_colsrc[pos]  = s * FTEXT;
            g_colsrcB[pos] = s * BBATCH;
            g_colw[pos]    = nm;
        }
    } else {
        int bidx = blockIdx.x - 625;          // 0..207
        int col0 = (bidx & 15) * 64;
        int sk = bidx >> 4;
        int kbase = sk * 128;
        const int BK = 16;
        int tx = tid & 15, ty = tid >> 4;
        float acc[4][4] = {};
        int r = tid >> 2, kq = (tid & 3) * 4;
        for (int t0 = 0; t0 < 128; t0 += BK) {
            float4 av = *(const float4*)(img + (size_t)r * FOUT + kbase + t0 + kq);
            As[kq + 0][r] = av.x; As[kq + 1][r] = av.y;
            As[kq + 2][r] = av.z; As[kq + 3][r] = av.w;
            float4 bv = *(const float4*)(W2 + (size_t)(col0 + r) * FOUT + kbase + t0 + kq);
            Bs[kq + 0][r] = bv.x; Bs[kq + 1][r] = bv.y;
            Bs[kq + 2][r] = bv.z; Bs[kq + 3][r] = bv.w;
            __syncthreads();
            #pragma unroll
            for (int k = 0; k < BK; k++) {
                float a[4], b[4];
                #pragma unroll
                for (int i = 0; i < 4; i++) a[i] = As[k][ty * 4 + i];
                #pragma unroll
                for (int j = 0; j < 4; j++) b[j] = Bs[k][tx * 4 + j];
                #pragma unroll
                for (int i = 0; i < 4; i++)
                    #pragma unroll
                    for (int j = 0; j < 4; j++)
                        acc[i][j] += a[i] * b[j];
            }
            __syncthreads();
        }
        float* cp = g_T1p + (size_t)sk * (BBATCH * FHID);
        #pragma unroll
        for (int i = 0; i < 4; i++) {
            int b = ty * 4 + i;
            #pragma unroll
            for (int j = 0; j < 4; j++)
                cp[(size_t)b * FHID + col0 + tx * 4 + j] = acc[i][j];
        }
    }
}

// ---------------- launch 3: Y = A @ X (R13 float2 gather, pre-scaled idx) ----
__global__ void k_aggY(const float* __restrict__ X) {
    __shared__ int   ss[128];
    __shared__ float sw[128];
    int n = blockIdx.x;
    int tid = threadIdx.x;
    int st = g_rowptr[n], en = g_rowptr[n + 1];
    float2 a0 = make_float2(0.f, 0.f);
    float2 a1 = make_float2(0.f, 0.f);
    bool hasT = (tid < 22);
    for (int e0 = st; e0 < en; e0 += 128) {
        int ne = min(128, en - e0);
        if (tid < ne) { ss[tid] = g_colsrc[e0 + tid]; sw[tid] = g_colw[e0 + tid]; }
        __syncthreads();
        int j = 0;
        for (; j + 2 <= ne; j += 2) {
            const float2* x0 = (const float2*)(X + ss[j]);
            const float2* x1 = (const float2*)(X + ss[j + 1]);
            float w0 = sw[j], w1 = sw[j + 1];
            float2 p0 = x0[tid], q0 = x1[tid];
            float2 p1 = make_float2(0.f, 0.f), q1 = make_float2(0.f, 0.f);
            if (hasT) { p1 = x0[128 + tid]; q1 = x1[128 + tid]; }
            a0.x += w0 * p0.x + w1 * q0.x;
            a0.y += w0 * p0.y + w1 * q0.y;
            a1.x += w0 * p1.x + w1 * q1.x;
            a1.y += w0 * p1.y + w1 * q1.y;
        }
        if (j < ne) {
            const float2* x0 = (const float2*)(X + ss[j]);
            float w0 = sw[j];
            float2 p0 = x0[tid];
            a0.x += w0 * p0.x;
            a0.y += w0 * p0.y;
            if (hasT) {
                float2 p1 = x0[128 + tid];
                a1.x += w0 * p1.x;
                a1.y += w0 * p1.y;
            }
        }
        __syncthreads();
    }
    float2* yr = (float2*)(g_Y + (size_t)n * FTEXT);
    yr[tid] = a0;
    if (hasT) yr[128 + tid] = a1;
}

// ---------------- plain-fp16 GEMM core, 128x64 CTA tile, 256 threads ---------
template<bool BIAS, bool LEAKY>
__device__ __forceinline__ void gemm_core(
    const float* __restrict__ A, int lda,
    const float* __restrict__ B, int ldb,
    float* __restrict__ C, int ldc,
    const float* __restrict__ bias,
    int M, int N, int K, int bx, int by, char* smem)
{
    const int A_BYTES = 128 * 80;
    const int B_BYTES = 64 * 80;
    const int STAGE   = A_BYTES + B_BYTES;   // 15360

    int tid  = threadIdx.x;
    int wid  = tid >> 5, lane = tid & 31;
    int wm   = wid & 3, wn = wid >> 2;
    int row0 = by * 128;
    int col0 = bx * 64;
    uint32_t smem_u = smem_to_u32(smem);

    float acc[2][4][4];
    #pragma unroll
    for (int mt = 0; mt < 2; mt++)
        #pragma unroll
        for (int nt = 0; nt < 4; nt++)
            #pragma unroll
            for (int q = 0; q < 4; q++) acc[mt][nt][q] = 0.f;

    float4 aR[4], bR[2];
    const int nT = (K + 31) >> 5;

    auto LDG = [&](int t) {
        int kb = t * 32;
        #pragma unroll
        for (int i = 0; i < 4; i++) {
            int idx = tid + i * 256;
            int r = idx >> 3, kk = (idx & 7) * 4;
            int row = row0 + r, kg = kb + kk;
            float4 v = make_float4(0.f, 0.f, 0.f, 0.f);
            if (row < M && kg < K) v = *(const float4*)(A + (size_t)row * lda + kg);
            aR[i] = v;
        }
        #pragma unroll
        for (int i = 0; i < 2; i++) {
            int idx = tid + i * 256;
            int c = idx >> 3, kk = (idx & 7) * 4;
            int col = col0 + c, kg = kb + kk;
            float4 v = make_float4(0.f, 0.f, 0.f, 0.f);
            if (col < N && kg < K) v = *(const float4*)(B + (size_t)col * ldb + kg);
            bR[i] = v;
        }
    };
    auto STS = [&](int s) {
        char* base = smem + s * STAGE;
        #pragma unroll
        for (int i = 0; i < 4; i++) {
            int idx = tid + i * 256;
            int r = idx >> 3, kk = (idx & 7) * 4;
            *(uint2*)(base + r * 80 + kk * 2) = f4_h(aR[i]);
        }
        #pragma unroll
        for (int i = 0; i < 2; i++) {
            int idx = tid + i * 256;
            int c = idx >> 3, kk = (idx & 7) * 4;
            *(uint2*)(base + A_BYTES + c * 80 + kk * 2) = f4_h(bR[i]);
        }
    };
    auto COMPUTE = [&](int s) {
        uint32_t sb = smem_u + s * STAGE;
        uint32_t aH = sb + (uint32_t)((wm * 32 + (lane & 15)) * 80 + (lane >> 4) * 16);
        uint32_t bH = sb + A_BYTES +
            (uint32_t)((wn * 32 + ((lane >> 4) & 1) * 8 + (lane & 7)) * 80 + ((lane >> 3) & 1) * 16);
        #pragma unroll
        for (int ks = 0; ks < 2; ks++) {
            uint32_t ah[2][4], bh[2][4];
            #pragma unroll
            for (int mt = 0; mt < 2; mt++)
                ldsm_x4(ah[mt], aH + mt * 16 * 80 + ks * 32);
            #pragma unroll
            for (int g = 0; g < 2; g++)
                ldsm_x4(bh[g], bH + g * 16 * 80 + ks * 32);
            #pragma unroll
            for (int mt = 0; mt < 2; mt++)
                #pragma unroll
                for (int nt = 0; nt < 4; nt++)
                    mma_f16(acc[mt][nt], ah[mt], &bh[nt >> 1][(nt & 1) * 2]);
        }
    };

    LDG(0);
    STS(0);
    if (nT > 1) LDG(1);
    __syncthreads();
    for (int t = 0; t < nT; t++) {
        COMPUTE(t & 1);
        if (t + 1 < nT) STS((t + 1) & 1);
        __syncthreads();
        if (t + 2 < nT) LDG(t + 2);
    }

    int rw = row0 + wm * 32;
    int cw = col0 + wn * 32;
    #pragma unroll
    for (int mt = 0; mt < 2; mt++) {
        #pragma unroll
        for (int half = 0; half < 2; half++) {
            int row = rw + mt * 16 + (lane >> 2) + half * 8;
            if (row >= M) continue;
            #pragma unroll
            for (int nt = 0; nt < 4; nt++) {
                int col = cw + nt * 8 + (lane & 3) * 2;
                if (col >= N) continue;
                float v0 = acc[mt][nt][half * 2 + 0];
                float v1 = acc[mt][nt][half * 2 + 1];
                if (BIAS) { v0 += bias[col]; v1 += bias[col + 1]; }
                if (LEAKY) {
                    v0 = (v0 >= 0.f) ? v0 : NEG_SLOPE * v0;
                    v1 = (v1 >= 0.f) ? v1 : NEG_SLOPE * v1;
                }
                float2 o; o.x = v0; o.y = v1;
                *(float2*)(C + (size_t)row * ldc + col) = o;
            }
        }
    }
}

// ---------------- launch 4: GEMM1 + T1 reduce + imgb2 (merged) ---------------
__global__ void __launch_bounds__(256, 2) k_gemm1_fused(
    const float* __restrict__ A, const float* __restrict__ B,
    float* __restrict__ C, const float* __restrict__ bias,
    const float* __restrict__ img, const float* __restrict__ b2)
{
    extern __shared__ char smem[];
    if (blockIdx.x < G1_GRID) {
        int bx = blockIdx.x & 15;
        int by = blockIdx.x >> 4;
        gemm_core<true, true>(A, FTEXT, B, FTEXT, C, FHID, bias,
                              NNODES, FHID, FTEXT, bx, by, smem);
    } else if (blockIdx.x < G1_GRID + 256) {
        int idx = (blockIdx.x - G1_GRID) * 256 + threadIdx.x;
        float acc = 0.f;
        #pragma unroll
        for (int s = 0; s < NSPLIT; s++)
            acc += g_T1p[(size_t)s * (BBATCH * FHID) + idx];
        g_T1[idx] = acc;
    } else {
        int wid = threadIdx.x >> 5, lane = threadIdx.x & 31;
        for (int i = 0; i < 8; i++) {
            int b = wid * 8 + i;
            float acc = 0.f;
            for (int k = lane; k < FOUT; k += 32)
                acc += img[(size_t)b * FOUT + k] * b2[k];
            #pragma unroll
            for (int off = 16; off > 0; off >>= 1)
                acc += __shfl_down_sync(0xffffffffu, acc, off);
            if (lane == 0) g_imgb2[b] = acc;
        }
    }
}

// ---------------- launch 5: T2 = X1 @ T1^T, 64-row tiles, plain fp16 ---------
__global__ void __launch_bounds__(128, 4) k_t2(
    const float* __restrict__ A, const float* __restrict__ B,
    float* __restrict__ C)
{
    extern __shared__ char smem[];
    const int A64 = 64 * 80;
    const int B64 = 64 * 80;
    const int STAGE = A64 + B64;           // 10240
    const int M = NNODES, K = FHID;

    int tid = threadIdx.x;
    int wid = tid >> 5, lane = tid & 31;
    int wm = wid & 1, wn = wid >> 1;
    int row0 = blockIdx.x * 64;
    uint32_t smem_u = smem_to_u32(smem);

    float acc[2][4][4];
    #pragma unroll
    for (int mt = 0; mt < 2; mt++)
        #pragma unroll
        for (int nt = 0; nt < 4; nt++)
            #pragma unroll
            for (int q = 0; q < 4; q++) acc[mt][nt][q] = 0.f;

    float4 aR[4], bR[4];
    const int nT = K >> 5;

    auto LDG = [&](int t) {
        int kb = t * 32;
        #pragma unroll
        for (int i = 0; i < 4; i++) {
            int idx = tid + i * 128;
            int r = idx >> 3, kk = (idx & 7) * 4;
            int row = row0 + r; row = (row < M) ? row : (M - 1);
            aR[i] = *(const float4*)(A + (size_t)row * K + kb + kk);
            bR[i] = *(const float4*)(B + (size_t)r * K + kb + kk);
        }
    };
    auto STS = [&](int s) {
        char* base = smem + s * STAGE;
        #pragma unroll
        for (int i = 0; i < 4; i++) {
            int idx = tid + i * 128;
            int r = idx >> 3, kk = (idx & 7) * 4;
            *(uint2*)(base + r * 80 + kk * 2) = f4_h(aR[i]);
            *(uint2*)(base + A64 + r * 80 + kk * 2) = f4_h(bR[i]);
        }
    };
    auto COMPUTE = [&](int s) {
        uint32_t sb = smem_u + s * STAGE;
        uint32_t aH = sb + (uint32_t)((wm * 32 + (lane & 15)) * 80 + (lane >> 4) * 16);
        uint32_t bH = sb + A64 +
            (uint32_t)((wn * 32 + ((lane >> 4) & 1) * 8 + (lane & 7)) * 80 + ((lane >> 3) & 1) * 16);
        #pragma unroll
        for (int ks = 0; ks < 2; ks++) {
            uint32_t ah[2][4], bh[2][4];
            #pragma unroll
            for (int mt = 0; mt < 2; mt++)
                ldsm_x4(ah[mt], aH + mt * 16 * 80 + ks * 32);
            #pragma unroll
            for (int g = 0; g < 2; g++)
                ldsm_x4(bh[g], bH + g * 16 * 80 + ks * 32);
            #pragma unroll
            for (int mt = 0; mt < 2; mt++)
                #pragma unroll
                for (int nt = 0; nt < 4; nt++)
                    mma_f16(acc[mt][nt], ah[mt], &bh[nt >> 1][(nt & 1) * 2]);
        }
    };

    LDG(0);
    STS(0);
    LDG(1);
    __syncthreads();
    for (int t = 0; t < nT; t++) {
        COMPUTE(t & 1);
        if (t + 1 < nT) STS((t + 1) & 1);
        __syncthreads();
        if (t + 2 < nT) LDG(t + 2);
    }

    int rw = row0 + wm * 32;
    int cw = wn * 32;
    #pragma unroll
    for (int mt = 0; mt < 2; mt++) {
        #pragma unroll
        for (int half = 0; half < 2; half++) {
            int row = rw + mt * 16 + (lane >> 2) + half * 8;
            if (row >= M) continue;
            #pragma unroll
            for (int nt = 0; nt < 4; nt++) {
                int col = cw + nt * 8 + (lane & 3) * 2;
                float2 o;
                o.x = acc[mt][nt][half * 2 + 0];
                o.y = acc[mt][nt][half * 2 + 1];
                *(float2*)(C + (size_t)row * BBATCH + col) = o;
            }
        }
    }
}

// ---------------- launch 6: output agg (float2/lane, warp-sync) + transpose --
__global__ void __launch_bounds__(256) k_aggOutT(float* __restrict__ out) {
    if (blockIdx.x >= 625) {
        int i = (blockIdx.x - 625) * 256 + threadIdx.x;
        if (i < NNODES) { g_deg[i] = 0.f; g_cnt[i] = 0; g_cursor[i] = 0; }
        return;
    }
    __shared__ float s[32][65];
    int n0 = blockIdx.x * 32;
    int tid = threadIdx.x;
    int slot = tid >> 5;                 // 0..7 (one warp per slot)
    int b2 = tid & 31;                   // float2 lane: cols 2*b2, 2*b2+1
    float bx = g_imgb2[2 * b2];
    float by = g_imgb2[2 * b2 + 1];
    #pragma unroll
    for (int rnd = 0; rnd < 4; rnd++) {
        int nl = rnd * 8 + slot;
        int n = n0 + nl;
        float ax = bx, ay = by;
        int st = g_rowptr[n], en = g_rowptr[n + 1];
        for (int e = st; e < en; e++) {
            float w = g_colw[e];
            float2 v = *(const float2*)(g_T2 + g_colsrcB[e] + 2 * b2);
            ax += w * v.x;
            ay += w * v.y;
        }
        s[nl][2 * b2]     = ax;
        s[nl][2 * b2 + 1] = ay;
    }
    __syncthreads();
    #pragma unroll
    for (int i = 0; i < 8; i++) {
        int idx = tid + i * 256;
        int bb = idx >> 5, nn = idx & 31;
        out[(size_t)bb * NNODES + n0 + nn] = s[nn][bb];
    }
}

// ---------------- launch ----------------
extern "C" void kernel_launch(void* const* d_in, const int* in_sizes, int n_in,
                              void* d_out, int out_size) {
    const float* img  = (const float*)d_in[0];
    const float* nf   = (const float*)d_in[1];
    const int*   esrc = (const int*)d_in[2];
    const int*   edst = (const int*)d_in[3];
    const float* ew   = (const float*)d_in[4];
    const float* W1   = (const float*)d_in[5];
    const float* b1   = (const float*)d_in[6];
    const float* W2   = (const float*)d_in[7];
    const float* b2   = (const float*)d_in[8];
    float* out = (float*)d_out;

    float *dY, *dX1, *dW1t, *dT1, *dT2;
    cudaGetSymbolAddress((void**)&dY,   g_Y);
    cudaGetSymbolAddress((void**)&dX1,  g_X1);
    cudaGetSymbolAddress((void**)&dW1t, g_W1t);
    cudaGetSymbolAddress((void**)&dT1,  g_T1);
    cudaGetSymbolAddress((void**)&dT2,  g_T2);

    const int SMEM1 = 30720;   // gemm_core: 2 stages x 15360
    const int SMEM2 = 20480;   // k_t2:      2 stages x 10240
    cudaFuncSetAttribute(k_gemm1_fused, cudaFuncAttributeMaxDynamicSharedMemorySize, SMEM1);
    cudaFuncSetAttribute(k_t2,          cudaFuncAttributeMaxDynamicSharedMemorySize, SMEM2);

    // 0: degree atomics + W1 transpose
    k_deg_w1t<<<625 + 320, 256>>>(edst, ew, W1);
    // 1: scan + dinv
    k_scandinv<<<1, 1024>>>();
    // 2: CSR fill (pre-scaled indices) + T1 split-K
    k_fill_t1<<<625 + 16 * NSPLIT, 256>>>(esrc, edst, ew, img, W2);
    // 3: layer-1 aggregation (float2 gather, R13 form, pre-scaled idx)
    k_aggY<<<NNODES, 128>>>(nf);
    // 4: GEMM1 + T1 reduce + imgb2 (plain fp16 MMA)
    k_gemm1_fused<<<G1_GRID + 256 + 1, 256, SMEM1>>>(dY, dW1t, dX1, b1, img, b2);
    // 5: T2 (plain fp16 MMA, 64-row tiles)
    k_t2<<<(NNODES + 63) / 64, 128, SMEM2>>>(dX1, dT1, dT2);
    // 6: output aggregation (float2/lane) + transpose + re-zero scratch
    k_aggOutT<<<625 + 79, 256>>>(out);
}

// round 16
// speedup vs baseline: 1.0180x; 1.0013x over previous
#include <cuda_runtime.h>
#include <cuda_fp16.h>
#include <cstdint>

#define NNODES 20000
#define NEDGES 160000
#define BBATCH 64
#define FTEXT  300
#define FHID   1024
#define FOUT   1664
#define NEG_SLOPE 0.2f
#define NSPLIT 13          // T1 split-K factor (13 * 128 = 1664)
#define G1_GRID (16 * 157) // GEMM1 CTAs

// ---------------- scratch (zero-initialized at load; re-zeroed each run) -----
__device__ float g_deg[NNODES];
__device__ float g_dinv[NNODES];
__device__ int   g_cnt[NNODES];
__device__ int   g_rowptr[NNODES + 1];
__device__ int   g_cursor[NNODES];
__device__ int2  g_edgeY[NEDGES];     // {src*FTEXT,  bitcast(w)}
__device__ int2  g_edgeB[NEDGES];     // {src*BBATCH, bitcast(w)}
__device__ float g_Y[(size_t)NNODES * FTEXT];
__device__ float g_X1[(size_t)NNODES * FHID];
__device__ float g_W1t[(size_t)FHID * FTEXT];
__device__ float g_T1p[(size_t)NSPLIT * BBATCH * FHID];
__device__ float g_T1[BBATCH * FHID];
__device__ float g_T2[(size_t)NNODES * BBATCH];
__device__ float g_imgb2[BBATCH];

// ---------------- PTX helpers (sm_80+ baseline only) ----------------
__device__ __forceinline__ uint32_t smem_to_u32(const void* p) {
    uint32_t a;
    asm("{ .reg .u64 t; cvta.to.shared.u64 t, %1; cvt.u32.u64 %0, t; }" : "=r"(a) : "l"(p));
    return a;
}
__device__ __forceinline__ void ldsm_x4(uint32_t* r, uint32_t addr) {
    asm volatile("ldmatrix.sync.aligned.m8n8.x4.shared.b16 {%0,%1,%2,%3}, [%4];"
        : "=r"(r[0]), "=r"(r[1]), "=r"(r[2]), "=r"(r[3]) : "r"(addr));
}
__device__ __forceinline__ void mma_f16(float* c, const uint32_t* a, const uint32_t* b) {
    asm volatile(
        "mma.sync.aligned.m16n8k16.row.col.f32.f16.f16.f32 "
        "{%0,%1,%2,%3}, {%4,%5,%6,%7}, {%8,%9}, {%0,%1,%2,%3};"
        : "+f"(c[0]), "+f"(c[1]), "+f"(c[2]), "+f"(c[3])
        : "r"(a[0]), "r"(a[1]), "r"(a[2]), "r"(a[3]), "r"(b[0]), "r"(b[1]));
}
__device__ __forceinline__ uint2 f4_h(float4 v) {
    __half2 h01(__float2half_rn(v.x), __float2half_rn(v.y));
    __half2 h23(__float2half_rn(v.z), __float2half_rn(v.w));
    uint2 h;
    h.x = *(uint32_t*)&h01; h.y = *(uint32_t*)&h23;
    return h;
}

// ---------------- launch 0: degree atomics + W1 transpose (independent) ------
__global__ void k_deg_w1t(const int* __restrict__ dst, const float* __restrict__ w,
                          const float* __restrict__ W1) {
    int tid = threadIdx.x;
    if (blockIdx.x < 625) {
        int e = blockIdx.x * 256 + tid;
        if (e < NEDGES) {
            int d = dst[e];
            atomicAdd(&g_deg[d], w[e]);
            atomicAdd(&g_cnt[d], 1);
        }
    } else {
        __shared__ float s[32][33];
        int bidx = blockIdx.x - 625;
        int n0 = (bidx & 31) * 32;
        int k0 = (bidx >> 5) * 32;
        int tx = tid & 31, ty = tid >> 5;
        #pragma unroll
        for (int i = 0; i < 32; i += 8) {
            int k = k0 + ty + i, n = n0 + tx;
            if (k < FTEXT) s[ty + i][tx] = W1[(size_t)k * FHID + n];
        }
        __syncthreads();
        #pragma unroll
        for (int i = 0; i < 32; i += 8) {
            int n = n0 + ty + i, k = k0 + tx;
            if (k < FTEXT) g_W1t[(size_t)n * FTEXT + k] = s[tx][ty + i];
        }
    }
}

// ---------------- launch 1: warp-shuffle scan + dinv ----------------
__global__ void k_scandinv() {
    const int CH = 20;
    __shared__ int wtot[32];
    __shared__ int s_total;
    int t = threadIdx.x;
    int lane = t & 31, wid = t >> 5;
    int base = t * CH;
    int loc[CH];
    int sum = 0;
    #pragma unroll
    for (int i = 0; i < CH; i++) {
        int idx = base + i;
        int v = 0;
        if (idx < NNODES) {
            v = g_cnt[idx];
            float d = g_deg[idx];
            g_dinv[idx] = (d > 0.f) ? rsqrtf(d) : 0.f;
        }
        loc[i] = sum;
        sum += v;
    }
    int inc = sum;
    #pragma unroll
    for (int off = 1; off < 32; off <<= 1) {
        int v = __shfl_up_sync(0xffffffffu, inc, off);
        if (lane >= off) inc += v;
    }
    if (lane == 31) wtot[wid] = inc;
    __syncthreads();
    if (wid == 0) {
        int v = wtot[lane];
        int wi = v;
        #pragma unroll
        for (int off = 1; off < 32; off <<= 1) {
            int u = __shfl_up_sync(0xffffffffu, wi, off);
            if (lane >= off) wi += u;
        }
        wtot[lane] = wi - v;
        if (lane == 31) s_total = wi;
    }
    __syncthreads();
    int off0 = wtot[wid] + inc - sum;
    #pragma unroll
    for (int i = 0; i < CH; i++) {
        int idx = base + i;
        if (idx < NNODES) g_rowptr[idx] = off0 + loc[i];
    }
    if (t == 0) g_rowptr[NNODES] = s_total;
}

// ---------------- launch 2: fill CSR (packed edges) + T1 split-K -------------
__global__ void __launch_bounds__(256) k_fill_t1(
    const int* __restrict__ src, const int* __restrict__ dst,
    const float* __restrict__ w,
    const float* __restrict__ img, const float* __restrict__ W2)
{
    __shared__ float As[16][64 + 1];
    __shared__ float Bs[16][64 + 1];
    int tid = threadIdx.x;
    if (blockIdx.x < 625) {
        int e = blockIdx.x * 256 + tid;
        if (e < NEDGES) {
            int s = src[e], d = dst[e];
            float nm = g_dinv[s] * w[e] * g_dinv[d];
            int pos = g_rowptr[d] + atomicAdd(&g_cursor[d], 1);
            g_edgeY[pos] = make_int2(s * FTEXT,  __float_as_int(nm));
            g_edgeB[pos] = make_int2(s * BBATCH, __float_as_int(nm));
        }
    } else {
        int bidx = blockIdx.x - 625;          // 0..207
        int col0 = (bidx & 15) * 64;
        int sk = bidx >> 4;
        int kbase = sk * 128;
        const int BK = 16;
        int tx = tid & 15, ty = tid >> 4;
        float acc[4][4] = {};
        int r = tid >> 2, kq = (tid & 3) * 4;
        for (int t0 = 0; t0 < 128; t0 += BK) {
            float4 av = *(const float4*)(img + (size_t)r * FOUT + kbase + t0 + kq);
            As[kq + 0][r] = av.x; As[kq + 1][r] = av.y;
            As[kq + 2][r] = av.z; As[kq + 3][r] = av.w;
            float4 bv = *(const float4*)(W2 + (size_t)(col0 + r) * FOUT + kbase + t0 + kq);
            Bs[kq + 0][r] = bv.x; Bs[kq + 1][r] = bv.y;
            Bs[kq + 2][r] = bv.z; Bs[kq + 3][r] = bv.w;
            __syncthreads();
            #pragma unroll
            for (int k = 0; k < BK; k++) {
                float a[4], b[4];
                #pragma unroll
                for (int i = 0; i < 4; i++) a[i] = As[k][ty * 4 + i];
                #pragma unroll
                for (int j = 0; j < 4; j++) b[j] = Bs[k][tx * 4 + j];
                #pragma unroll
                for (int i = 0; i < 4; i++)
                    #pragma unroll
                    for (int j = 0; j < 4; j++)
                        acc[i][j] += a[i] * b[j];
            }
            __syncthreads();
        }
        float* cp = g_T1p + (size_t)sk * (BBATCH * FHID);
        #pragma unroll
        for (int i = 0; i < 4; i++) {
            int b = ty * 4 + i;
            #pragma unroll
            for (int j = 0; j < 4; j++)
                cp[(size_t)b * FHID + col0 + tx * 4 + j] = acc[i][j];
        }
    }
}

// ---------------- launch 3: Y = A @ X — barrier-free uniform-edge gather -----
__global__ void k_aggY(const float* __restrict__ X) {
    int n = blockIdx.x;
    int tid = threadIdx.x;
    int st = g_rowptr[n], en = g_rowptr[n + 1];
    float2 a0 = make_float2(0.f, 0.f);     // cols 2t, 2t+1
    float2 a1 = make_float2(0.f, 0.f);     // cols 256+2t (t<22)
    bool hasT = (tid < 22);
    int e = st;
    for (; e + 2 <= en; e += 2) {
        int2 e0 = g_edgeY[e];
        int2 e1 = g_edgeY[e + 1];
        float w0 = __int_as_float(e0.y), w1 = __int_as_float(e1.y);
        const float2* x0 = (const float2*)(X + e0.x);
        const float2* x1 = (const float2*)(X + e1.x);
        float2 p0 = x0[tid], q0 = x1[tid];
        float2 p1 = make_float2(0.f, 0.f), q1 = make_float2(0.f, 0.f);
        if (hasT) { p1 = x0[128 + tid]; q1 = x1[128 + tid]; }
        a0.x += w0 * p0.x + w1 * q0.x;
        a0.y += w0 * p0.y + w1 * q0.y;
        a1.x += w0 * p1.x + w1 * q1.x;
        a1.y += w0 * p1.y + w1 * q1.y;
    }
    if (e < en) {
        int2 e0 = g_edgeY[e];
        float w0 = __int_as_float(e0.y);
        const float2* x0 = (const float2*)(X + e0.x);
        float2 p0 = x0[tid];
        a0.x += w0 * p0.x;
        a0.y += w0 * p0.y;
        if (hasT) {
            float2 p1 = x0[128 + tid];
            a1.x += w0 * p1.x;
            a1.y += w0 * p1.y;
        }
    }
    float2* yr = (float2*)(g_Y + (size_t)n * FTEXT);
    yr[tid] = a0;
    if (hasT) yr[128 + tid] = a1;
}

// ---------------- plain-fp16 GEMM core, 128x64 CTA tile, 256 threads ---------
template<bool BIAS, bool LEAKY>
__device__ __forceinline__ void gemm_core(
    const float* __restrict__ A, int lda,
    const float* __restrict__ B, int ldb,
    float* __restrict__ C, int ldc,
    const float* __restrict__ bias,
    int M, int N, int K, int bx, int by, char* smem)
{
    const int A_BYTES = 128 * 80;
    const int B_BYTES = 64 * 80;
    const int STAGE   = A_BYTES + B_BYTES;   // 15360

    int tid  = threadIdx.x;
    int wid  = tid >> 5, lane = tid & 31;
    int wm   = wid & 3, wn = wid >> 2;
    int row0 = by * 128;
    int col0 = bx * 64;
    uint32_t smem_u = smem_to_u32(smem);

    float acc[2][4][4];
    #pragma unroll
    for (int mt = 0; mt < 2; mt++)
        #pragma unroll
        for (int nt = 0; nt < 4; nt++)
            #pragma unroll
            for (int q = 0; q < 4; q++) acc[mt][nt][q] = 0.f;

    float4 aR[4], bR[2];
    const int nT = (K + 31) >> 5;

    auto LDG = [&](int t) {
        int kb = t * 32;
        #pragma unroll
        for (int i = 0; i < 4; i++) {
            int idx = tid + i * 256;
            int r = idx >> 3, kk = (idx & 7) * 4;
            int row = row0 + r, kg = kb + kk;
            float4 v = make_float4(0.f, 0.f, 0.f, 0.f);
            if (row < M && kg < K) v = *(const float4*)(A + (size_t)row * lda + kg);
            aR[i] = v;
        }
        #pragma unroll
        for (int i = 0; i < 2; i++) {
            int idx = tid + i * 256;
            int c = idx >> 3, kk = (idx & 7) * 4;
            int col = col0 + c, kg = kb + kk;
            float4 v = make_float4(0.f, 0.f, 0.f, 0.f);
            if (col < N && kg < K) v = *(const float4*)(B + (size_t)col * ldb + kg);
            bR[i] = v;
        }
    };
    auto STS = [&](int s) {
        char* base = smem + s * STAGE;
        #pragma unroll
        for (int i = 0; i < 4; i++) {
            int idx = tid + i * 256;
            int r = idx >> 3, kk = (idx & 7) * 4;
            *(uint2*)(base + r * 80 + kk * 2) = f4_h(aR[i]);
        }
        #pragma unroll
        for (int i = 0; i < 2; i++) {
            int idx = tid + i * 256;
            int c = idx >> 3, kk = (idx & 7) * 4;
            *(uint2*)(base + A_BYTES + c * 80 + kk * 2) = f4_h(bR[i]);
        }
    };
    auto COMPUTE = [&](int s) {
        uint32_t sb = smem_u + s * STAGE;
        uint32_t aH = sb + (uint32_t)((wm * 32 + (lane & 15)) * 80 + (lane >> 4) * 16);
        uint32_t bH = sb + A_BYTES +
            (uint32_t)((wn * 32 + ((lane >> 4) & 1) * 8 + (lane & 7)) * 80 + ((lane >> 3) & 1) * 16);
        #pragma unroll
        for (int ks = 0; ks < 2; ks++) {
            uint32_t ah[2][4], bh[2][4];
            #pragma unroll
            for (int mt = 0; mt < 2; mt++)
                ldsm_x4(ah[mt], aH + mt * 16 * 80 + ks * 32);
            #pragma unroll
            for (int g = 0; g < 2; g++)
                ldsm_x4(bh[g], bH + g * 16 * 80 + ks * 32);
            #pragma unroll
            for (int mt = 0; mt < 2; mt++)
                #pragma unroll
                for (int nt = 0; nt < 4; nt++)
                    mma_f16(acc[mt][nt], ah[mt], &bh[nt >> 1][(nt & 1) * 2]);
        }
    };

    LDG(0);
    STS(0);
    if (nT > 1) LDG(1);
    __syncthreads();
    for (int t = 0; t < nT; t++) {
        COMPUTE(t & 1);
        if (t + 1 < nT) STS((t + 1) & 1);
        __syncthreads();
        if (t + 2 < nT) LDG(t + 2);
    }

    int rw = row0 + wm * 32;
    int cw = col0 + wn * 32;
    #pragma unroll
    for (int mt = 0; mt < 2; mt++) {
        #pragma unroll
        for (int half = 0; half < 2; half++) {
            int row = rw + mt * 16 + (lane >> 2) + half * 8;
            if (row >= M) continue;
            #pragma unroll
            for (int nt = 0; nt < 4; nt++) {
                int col = cw + nt * 8 + (lane & 3) * 2;
                if (col >= N) continue;
                float v0 = acc[mt][nt][half * 2 + 0];
                float v1 = acc[mt][nt][half * 2 + 1];
                if (BIAS) { v0 += bias[col]; v1 += bias[col + 1]; }
                if (LEAKY) {
                    v0 = (v0 >= 0.f) ? v0 : NEG_SLOPE * v0;
                    v1 = (v1 >= 0.f) ? v1 : NEG_SLOPE * v1;
                }
                float2 o; o.x = v0; o.y = v1;
                *(float2*)(C + (size_t)row * ldc + col) = o;
            }
        }
    }
}

// ---------------- launch 4: GEMM1 + T1 reduce + imgb2 (merged) ---------------
__global__ void __launch_bounds__(256, 2) k_gemm1_fused(
    const float* __restrict__ A, const float* __restrict__ B,
    float* __restrict__ C, const float* __restrict__ bias,
    const float* __restrict__ img, const float* __restrict__ b2)
{
    extern __shared__ char smem[];
    if (blockIdx.x < G1_GRID) {
        int bx = blockIdx.x & 15;
        int by = blockIdx.x >> 4;
        gemm_core<true, true>(A, FTEXT, B, FTEXT, C, FHID, bias,
                              NNODES, FHID, FTEXT, bx, by, smem);
    } else if (blockIdx.x < G1_GRID + 256) {
        int idx = (blockIdx.x - G1_GRID) * 256 + threadIdx.x;
        float acc = 0.f;
        #pragma unroll
        for (int s = 0; s < NSPLIT; s++)
            acc += g_T1p[(size_t)s * (BBATCH * FHID) + idx];
        g_T1[idx] = acc;
    } else {
        int wid = threadIdx.x >> 5, lane = threadIdx.x & 31;
        for (int i = 0; i < 8; i++) {
            int b = wid * 8 + i;
            float acc = 0.f;
            for (int k = lane; k < FOUT; k += 32)
                acc += img[(size_t)b * FOUT + k] * b2[k];
            #pragma unroll
            for (int off = 16; off > 0; off >>= 1)
                acc += __shfl_down_sync(0xffffffffu, acc, off);
            if (lane == 0) g_imgb2[b] = acc;
        }
    }
}

// ---------------- launch 5: T2 = X1 @ T1^T, 64-row tiles, plain fp16 ---------
__global__ void __launch_bounds__(128, 4) k_t2(
    const float* __restrict__ A, const float* __restrict__ B,
    float* __restrict__ C)
{
    extern __shared__ char smem[];
    const int A64 = 64 * 80;
    const int B64 = 64 * 80;
    const int STAGE = A64 + B64;           // 10240
    const int M = NNODES, K = FHID;

    int tid = threadIdx.x;
    int wid = tid >> 5, lane = tid & 31;
    int wm = wid & 1, wn = wid >> 1;
    int row0 = blockIdx.x * 64;
    uint32_t smem_u = smem_to_u32(smem);

    float acc[2][4][4];
    #pragma unroll
    for (int mt = 0; mt < 2; mt++)
        #pragma unroll
        for (int nt = 0; nt < 4; nt++)
            #pragma unroll
            for (int q = 0; q < 4; q++) acc[mt][nt][q] = 0.f;

    float4 aR[4], bR[4];
    const int nT = K >> 5;

    auto LDG = [&](int t) {
        int kb = t * 32;
        #pragma unroll
        for (int i = 0; i < 4; i++) {
            int idx = tid + i * 128;
            int r = idx >> 3, kk = (idx & 7) * 4;
            int row = row0 + r; row = (row < M) ? row : (M - 1);
            aR[i] = *(const float4*)(A + (size_t)row * K + kb + kk);
            bR[i] = *(const float4*)(B + (size_t)r * K + kb + kk);
        }
    };
    auto STS = [&](int s) {
        char* base = smem + s * STAGE;
        #pragma unroll
        for (int i = 0; i < 4; i++) {
            int idx = tid + i * 128;
            int r = idx >> 3, kk = (idx & 7) * 4;
            *(uint2*)(base + r * 80 + kk * 2) = f4_h(aR[i]);
            *(uint2*)(base + A64 + r * 80 + kk * 2) = f4_h(bR[i]);
        }
    };
    auto COMPUTE = [&](int s) {
        uint32_t sb = smem_u + s * STAGE;
        uint32_t aH = sb + (uint32_t)((wm * 32 + (lane & 15)) * 80 + (lane >> 4) * 16);
        uint32_t bH = sb + A64 +
            (uint32_t)((wn * 32 + ((lane >> 4) & 1) * 8 + (lane & 7)) * 80 + ((lane >> 3) & 1) * 16);
        #pragma unroll
        for (int ks = 0; ks < 2; ks++) {
            uint32_t ah[2][4], bh[2][4];
            #pragma unroll
            for (int mt = 0; mt < 2; mt++)
                ldsm_x4(ah[mt], aH + mt * 16 * 80 + ks * 32);
            #pragma unroll
            for (int g = 0; g < 2; g++)
                ldsm_x4(bh[g], bH + g * 16 * 80 + ks * 32);
            #pragma unroll
            for (int mt = 0; mt < 2; mt++)
                #pragma unroll
                for (int nt = 0; nt < 4; nt++)
                    mma_f16(acc[mt][nt], ah[mt], &bh[nt >> 1][(nt & 1) * 2]);
        }
    };

    LDG(0);
    STS(0);
    LDG(1);
    __syncthreads();
    for (int t = 0; t < nT; t++) {
        COMPUTE(t & 1);
        if (t + 1 < nT) STS((t + 1) & 1);
        __syncthreads();
        if (t + 2 < nT) LDG(t + 2);
    }

    int rw = row0 + wm * 32;
    int cw = wn * 32;
    #pragma unroll
    for (int mt = 0; mt < 2; mt++) {
        #pragma unroll
        for (int half = 0; half < 2; half++) {
            int row = rw + mt * 16 + (lane >> 2) + half * 8;
            if (row >= M) continue;
            #pragma unroll
            for (int nt = 0; nt < 4; nt++) {
                int col = cw + nt * 8 + (lane & 3) * 2;
                float2 o;
                o.x = acc[mt][nt][half * 2 + 0];
                o.y = acc[mt][nt][half * 2 + 1];
                *(float2*)(C + (size_t)row * BBATCH + col) = o;
            }
        }
    }
}

// ---------------- launch 6: output agg (packed edges) + transpose ------------
__global__ void __launch_bounds__(256) k_aggOutT(float* __restrict__ out) {
    if (blockIdx.x >= 625) {
        int i = (blockIdx.x - 625) * 256 + threadIdx.x;
        if (i < NNODES) { g_deg[i] = 0.f; g_cnt[i] = 0; g_cursor[i] = 0; }
        return;
    }
    __shared__ float s[32][65];
    int n0 = blockIdx.x * 32;
    int tid = threadIdx.x;
    int slot = tid >> 5;                 // 0..7 (one warp per slot)
    int b2 = tid & 31;                   // float2 lane
    float bx = g_imgb2[2 * b2];
    float by = g_imgb2[2 * b2 + 1];
    #pragma unroll
    for (int rnd = 0; rnd < 4; rnd++) {
        int nl = rnd * 8 + slot;
        int n = n0 + nl;
        float ax = bx, ay = by;
        int st = g_rowptr[n], en = g_rowptr[n + 1];
        for (int e = st; e < en; e++) {
            int2 ed = g_edgeB[e];
            float w = __int_as_float(ed.y);
            float2 v = *(const float2*)(g_T2 + ed.x + 2 * b2);
            ax += w * v.x;
            ay += w * v.y;
        }
        s[nl][2 * b2]     = ax;
        s[nl][2 * b2 + 1] = ay;
    }
    __syncthreads();
    #pragma unroll
    for (int i = 0; i < 8; i++) {
        int idx = tid + i * 256;
        int bb = idx >> 5, nn = idx & 31;
        out[(size_t)bb * NNODES + n0 + nn] = s[nn][bb];
    }
}

// ---------------- launch ----------------
extern "C" void kernel_launch(void* const* d_in, const int* in_sizes, int n_in,
                              void* d_out, int out_size) {
    const float* img  = (const float*)d_in[0];
    const float* nf   = (const float*)d_in[1];
    const int*   esrc = (const int*)d_in[2];
    const int*   edst = (const int*)d_in[3];
    const float* ew   = (const float*)d_in[4];
    const float* W1   = (const float*)d_in[5];
    const float* b1   = (const float*)d_in[6];
    const float* W2   = (const float*)d_in[7];
    const float* b2   = (const float*)d_in[8];
    float* out = (float*)d_out;

    float *dY, *dX1, *dW1t, *dT1, *dT2;
    cudaGetSymbolAddress((void**)&dY,   g_Y);
    cudaGetSymbolAddress((void**)&dX1,  g_X1);
    cudaGetSymbolAddress((void**)&dW1t, g_W1t);
    cudaGetSymbolAddress((void**)&dT1,  g_T1);
    cudaGetSymbolAddress((void**)&dT2,  g_T2);

    const int SMEM1 = 30720;   // gemm_core: 2 stages x 15360
    const int SMEM2 = 20480;   // k_t2:      2 stages x 10240
    cudaFuncSetAttribute(k_gemm1_fused, cudaFuncAttributeMaxDynamicSharedMemorySize, SMEM1);
    cudaFuncSetAttribute(k_t2,          cudaFuncAttributeMaxDynamicSharedMemorySize, SMEM2);

    // 0: degree atomics + W1 transpose
    k_deg_w1t<<<625 + 320, 256>>>(edst, ew, W1);
    // 1: scan + dinv
    k_scandinv<<<1, 1024>>>();
    // 2: CSR fill (packed edges) + T1 split-K
    k_fill_t1<<<625 + 16 * NSPLIT, 256>>>(esrc, edst, ew, img, W2);
    // 3: layer-1 aggregation (barrier-free uniform-edge gather)
    k_aggY<<<NNODES, 128>>>(nf);
    // 4: GEMM1 + T1 reduce + imgb2 (plain fp16 MMA)
    k_gemm1_fused<<<G1_GRID + 256 + 1, 256, SMEM1>>>(dY, dW1t, dX1, b1, img, b2);
    // 5: T2 (plain fp16 MMA, 64-row tiles)
    k_t2<<<(NNODES + 63) / 64, 128, SMEM2>>>(dX1, dT1, dT2);
    // 6: output aggregation (packed edges) + transpose + re-zero scratch
    k_aggOutT<<<625 + 79, 256>>>(out);
}

// round 17
// speedup vs baseline: 1.0271x; 1.0090x over previous
#include <cuda_runtime.h>
#include <cuda_fp16.h>
#include <cstdint>

#define NNODES 20000
#define NEDGES 160000
#define BBATCH 64
#define FTEXT  300
#define FHID   1024
#define FOUT   1664
#define NEG_SLOPE 0.2f
#define NSPLIT 13          // T1 split-K factor (13 * 128 = 1664)
#define G1_GRID (16 * 157) // GEMM1 CTAs
#define T1_BLKS (16 * NSPLIT)   // 208

// ---------------- scratch (zero-initialized at load; re-zeroed each run) -----
__device__ float g_deg[NNODES];
__device__ float g_dinv[NNODES];
__device__ int   g_cnt[NNODES];
__device__ int   g_rowptr[NNODES + 1];
__device__ int   g_cursor[NNODES];
__device__ int2  g_edgeY[NEDGES];     // {src*FTEXT,  bitcast(w)}
__device__ int2  g_edgeB[NEDGES];     // {src*BBATCH, bitcast(w)}
__device__ float g_Y[(size_t)NNODES * FTEXT];
__device__ float g_X1[(size_t)NNODES * FHID];
__device__ float g_W1t[(size_t)FHID * FTEXT];
__device__ float g_T1p[(size_t)NSPLIT * BBATCH * FHID];
__device__ float g_T1[BBATCH * FHID];
__device__ float g_T2[(size_t)NNODES * BBATCH];
__device__ float g_imgb2[BBATCH];

// ---------------- PTX helpers (sm_80+ baseline only) ----------------
__device__ __forceinline__ uint32_t smem_to_u32(const void* p) {
    uint32_t a;
    asm("{ .reg .u64 t; cvta.to.shared.u64 t, %1; cvt.u32.u64 %0, t; }" : "=r"(a) : "l"(p));
    return a;
}
__device__ __forceinline__ void ldsm_x4(uint32_t* r, uint32_t addr) {
    asm volatile("ldmatrix.sync.aligned.m8n8.x4.shared.b16 {%0,%1,%2,%3}, [%4];"
        : "=r"(r[0]), "=r"(r[1]), "=r"(r[2]), "=r"(r[3]) : "r"(addr));
}
__device__ __forceinline__ void mma_f16(float* c, const uint32_t* a, const uint32_t* b) {
    asm volatile(
        "mma.sync.aligned.m16n8k16.row.col.f32.f16.f16.f32 "
        "{%0,%1,%2,%3}, {%4,%5,%6,%7}, {%8,%9}, {%0,%1,%2,%3};"
        : "+f"(c[0]), "+f"(c[1]), "+f"(c[2]), "+f"(c[3])
        : "r"(a[0]), "r"(a[1]), "r"(a[2]), "r"(a[3]), "r"(b[0]), "r"(b[1]));
}
__device__ __forceinline__ uint2 f4_h(float4 v) {
    __half2 h01(__float2half_rn(v.x), __float2half_rn(v.y));
    __half2 h23(__float2half_rn(v.z), __float2half_rn(v.w));
    uint2 h;
    h.x = *(uint32_t*)&h01; h.y = *(uint32_t*)&h23;
    return h;
}

// ---------------- launch 0: W1 transpose FIRST, then degree atomics ----------
__global__ void k_deg_w1t(const int* __restrict__ dst, const float* __restrict__ w,
                          const float* __restrict__ W1) {
    int tid = threadIdx.x;
    if (blockIdx.x < 320) {
        __shared__ float s[32][33];
        int bidx = blockIdx.x;
        int n0 = (bidx & 31) * 32;
        int k0 = (bidx >> 5) * 32;
        int tx = tid & 31, ty = tid >> 5;
        #pragma unroll
        for (int i = 0; i < 32; i += 8) {
            int k = k0 + ty + i, n = n0 + tx;
            if (k < FTEXT) s[ty + i][tx] = W1[(size_t)k * FHID + n];
        }
        __syncthreads();
        #pragma unroll
        for (int i = 0; i < 32; i += 8) {
            int n = n0 + ty + i, k = k0 + tx;
            if (k < FTEXT) g_W1t[(size_t)n * FTEXT + k] = s[tx][ty + i];
        }
    } else {
        int e = (blockIdx.x - 320) * 256 + tid;
        if (e < NEDGES) {
            int d = dst[e];
            atomicAdd(&g_deg[d], w[e]);
            atomicAdd(&g_cnt[d], 1);
        }
    }
}

// ---------------- launch 1: warp-shuffle scan + dinv ----------------
__global__ void k_scandinv() {
    const int CH = 20;
    __shared__ int wtot[32];
    __shared__ int s_total;
    int t = threadIdx.x;
    int lane = t & 31, wid = t >> 5;
    int base = t * CH;
    int loc[CH];
    int sum = 0;
    #pragma unroll
    for (int i = 0; i < CH; i++) {
        int idx = base + i;
        int v = 0;
        if (idx < NNODES) {
            v = g_cnt[idx];
            float d = g_deg[idx];
            g_dinv[idx] = (d > 0.f) ? rsqrtf(d) : 0.f;
        }
        loc[i] = sum;
        sum += v;
    }
    int inc = sum;
    #pragma unroll
    for (int off = 1; off < 32; off <<= 1) {
        int v = __shfl_up_sync(0xffffffffu, inc, off);
        if (lane >= off) inc += v;
    }
    if (lane == 31) wtot[wid] = inc;
    __syncthreads();
    if (wid == 0) {
        int v = wtot[lane];
        int wi = v;
        #pragma unroll
        for (int off = 1; off < 32; off <<= 1) {
            int u = __shfl_up_sync(0xffffffffu, wi, off);
            if (lane >= off) wi += u;
        }
        wtot[lane] = wi - v;
        if (lane == 31) s_total = wi;
    }
    __syncthreads();
    int off0 = wtot[wid] + inc - sum;
    #pragma unroll
    for (int i = 0; i < CH; i++) {
        int idx = base + i;
        if (idx < NNODES) g_rowptr[idx] = off0 + loc[i];
    }
    if (t == 0) g_rowptr[NNODES] = s_total;
}

// ---------------- launch 2: T1 split-K FIRST, then CSR fill ------------------
__global__ void __launch_bounds__(256) k_fill_t1(
    const int* __restrict__ src, const int* __restrict__ dst,
    const float* __restrict__ w,
    const float* __restrict__ img, const float* __restrict__ W2)
{
    __shared__ float As[16][64 + 1];
    __shared__ float Bs[16][64 + 1];
    int tid = threadIdx.x;
    if (blockIdx.x < T1_BLKS) {
        // T1 partials (long blocks first for wave-1 placement)
        int bidx = blockIdx.x;                // 0..207
        int col0 = (bidx & 15) * 64;
        int sk = bidx >> 4;
        int kbase = sk * 128;
        const int BK = 16;
        int tx = tid & 15, ty = tid >> 4;
        float acc[4][4] = {};
        int r = tid >> 2, kq = (tid & 3) * 4;
        for (int t0 = 0; t0 < 128; t0 += BK) {
            float4 av = *(const float4*)(img + (size_t)r * FOUT + kbase + t0 + kq);
            As[kq + 0][r] = av.x; As[kq + 1][r] = av.y;
            As[kq + 2][r] = av.z; As[kq + 3][r] = av.w;
            float4 bv = *(const float4*)(W2 + (size_t)(col0 + r) * FOUT + kbase + t0 + kq);
            Bs[kq + 0][r] = bv.x; Bs[kq + 1][r] = bv.y;
            Bs[kq + 2][r] = bv.z; Bs[kq + 3][r] = bv.w;
            __syncthreads();
            #pragma unroll
            for (int k = 0; k < BK; k++) {
                float a[4], b[4];
                #pragma unroll
                for (int i = 0; i < 4; i++) a[i] = As[k][ty * 4 + i];
                #pragma unroll
                for (int j = 0; j < 4; j++) b[j] = Bs[k][tx * 4 + j];
                #pragma unroll
                for (int i = 0; i < 4; i++)
                    #pragma unroll
                    for (int j = 0; j < 4; j++)
                        acc[i][j] += a[i] * b[j];
            }
            __syncthreads();
        }
        float* cp = g_T1p + (size_t)sk * (BBATCH * FHID);
        #pragma unroll
        for (int i = 0; i < 4; i++) {
            int b = ty * 4 + i;
            #pragma unroll
            for (int j = 0; j < 4; j++)
                cp[(size_t)b * FHID + col0 + tx * 4 + j] = acc[i][j];
        }
    } else {
        int e = (blockIdx.x - T1_BLKS) * 256 + tid;
        if (e < NEDGES) {
            int s = src[e], d = dst[e];
            float nm = g_dinv[s] * w[e] * g_dinv[d];
            int pos = g_rowptr[d] + atomicAdd(&g_cursor[d], 1);
            g_edgeY[pos] = make_int2(s * FTEXT,  __float_as_int(nm));
            g_edgeB[pos] = make_int2(s * BBATCH, __float_as_int(nm));
        }
    }
}

// ---------------- launch 3: Y = A @ X — prefetched barrier-free gather -------
__global__ void k_aggY(const float* __restrict__ X) {
    int n = blockIdx.x;
    int tid = threadIdx.x;
    int st = g_rowptr[n], en = g_rowptr[n + 1];
    float2 a0 = make_float2(0.f, 0.f);
    float2 a1 = make_float2(0.f, 0.f);
    bool hasT = (tid < 22);
    int e = st;
    int rem = en - st;
    int2 c0, c1;
    if (rem >= 2) { c0 = g_edgeY[e]; c1 = g_edgeY[e + 1]; }
    while (rem >= 2) {
        int2 n0 = c0, n1 = c1;               // consumed this iter
        if (rem >= 4) {                      // prefetch next pair
            c0 = g_edgeY[e + 2];
            c1 = g_edgeY[e + 3];
        }
        float w0 = __int_as_float(n0.y), w1 = __int_as_float(n1.y);
        const float2* x0 = (const float2*)(X + n0.x);
        const float2* x1 = (const float2*)(X + n1.x);
        float2 p0 = x0[tid], q0 = x1[tid];
        float2 p1 = make_float2(0.f, 0.f), q1 = make_float2(0.f, 0.f);
        if (hasT) { p1 = x0[128 + tid]; q1 = x1[128 + tid]; }
        a0.x += w0 * p0.x + w1 * q0.x;
        a0.y += w0 * p0.y + w1 * q0.y;
        a1.x += w0 * p1.x + w1 * q1.x;
        a1.y += w0 * p1.y + w1 * q1.y;
        e += 2;
        rem -= 2;
    }
    if (rem) {
        int2 e0 = g_edgeY[e];
        float w0 = __int_as_float(e0.y);
        const float2* x0 = (const float2*)(X + e0.x);
        float2 p0 = x0[tid];
        a0.x += w0 * p0.x;
        a0.y += w0 * p0.y;
        if (hasT) {
            float2 p1 = x0[128 + tid];
            a1.x += w0 * p1.x;
            a1.y += w0 * p1.y;
        }
    }
    float2* yr = (float2*)(g_Y + (size_t)n * FTEXT);
    yr[tid] = a0;
    if (hasT) yr[128 + tid] = a1;
}

// ---------------- plain-fp16 GEMM core, 128x64 CTA tile, 256 threads ---------
template<bool BIAS, bool LEAKY>
__device__ __forceinline__ void gemm_core(
    const float* __restrict__ A, int lda,
    const float* __restrict__ B, int ldb,
    float* __restrict__ C, int ldc,
    const float* __restrict__ bias,
    int M, int N, int K, int bx, int by, char* smem)
{
    const int A_BYTES = 128 * 80;
    const int B_BYTES = 64 * 80;
    const int STAGE   = A_BYTES + B_BYTES;   // 15360

    int tid  = threadIdx.x;
    int wid  = tid >> 5, lane = tid & 31;
    int wm   = wid & 3, wn = wid >> 2;
    int row0 = by * 128;
    int col0 = bx * 64;
    uint32_t smem_u = smem_to_u32(smem);

    float acc[2][4][4];
    #pragma unroll
    for (int mt = 0; mt < 2; mt++)
        #pragma unroll
        for (int nt = 0; nt < 4; nt++)
            #pragma unroll
            for (int q = 0; q < 4; q++) acc[mt][nt][q] = 0.f;

    float4 aR[4], bR[2];
    const int nT = (K + 31) >> 5;

    auto LDG = [&](int t) {
        int kb = t * 32;
        #pragma unroll
        for (int i = 0; i < 4; i++) {
            int idx = tid + i * 256;
            int r = idx >> 3, kk = (idx & 7) * 4;
            int row = row0 + r, kg = kb + kk;
            float4 v = make_float4(0.f, 0.f, 0.f, 0.f);
            if (row < M && kg < K) v = *(const float4*)(A + (size_t)row * lda + kg);
            aR[i] = v;
        }
        #pragma unroll
        for (int i = 0; i < 2; i++) {
            int idx = tid + i * 256;
            int c = idx >> 3, kk = (idx & 7) * 4;
            int col = col0 + c, kg = kb + kk;
            float4 v = make_float4(0.f, 0.f, 0.f, 0.f);
            if (col < N && kg < K) v = *(const float4*)(B + (size_t)col * ldb + kg);
            bR[i] = v;
        }
    };
    auto STS = [&](int s) {
        char* base = smem + s * STAGE;
        #pragma unroll
        for (int i = 0; i < 4; i++) {
            int idx = tid + i * 256;
            int r = idx >> 3, kk = (idx & 7) * 4;
            *(uint2*)(base + r * 80 + kk * 2) = f4_h(aR[i]);
        }
        #pragma unroll
        for (int i = 0; i < 2; i++) {
            int idx = tid + i * 256;
            int c = idx >> 3, kk = (idx & 7) * 4;
            *(uint2*)(base + A_BYTES + c * 80 + kk * 2) = f4_h(bR[i]);
        }
    };
    auto COMPUTE = [&](int s) {
        uint32_t sb = smem_u + s * STAGE;
        uint32_t aH = sb + (uint32_t)((wm * 32 + (lane & 15)) * 80 + (lane >> 4) * 16);
        uint32_t bH = sb + A_BYTES +
            (uint32_t)((wn * 32 + ((lane >> 4) & 1) * 8 + (lane & 7)) * 80 + ((lane >> 3) & 1) * 16);
        #pragma unroll
        for (int ks = 0; ks < 2; ks++) {
            uint32_t ah[2][4], bh[2][4];
            #pragma unroll
            for (int mt = 0; mt < 2; mt++)
                ldsm_x4(ah[mt], aH + mt * 16 * 80 + ks * 32);
            #pragma unroll
            for (int g = 0; g < 2; g++)
                ldsm_x4(bh[g], bH + g * 16 * 80 + ks * 32);
            #pragma unroll
            for (int mt = 0; mt < 2; mt++)
                #pragma unroll
                for (int nt = 0; nt < 4; nt++)
                    mma_f16(acc[mt][nt], ah[mt], &bh[nt >> 1][(nt & 1) * 2]);
        }
    };

    LDG(0);
    STS(0);
    if (nT > 1) LDG(1);
    __syncthreads();
    for (int t = 0; t < nT; t++) {
        COMPUTE(t & 1);
        if (t + 1 < nT) STS((t + 1) & 1);
        __syncthreads();
        if (t + 2 < nT) LDG(t + 2);
    }

    int rw = row0 + wm * 32;
    int cw = col0 + wn * 32;
    #pragma unroll
    for (int mt = 0; mt < 2; mt++) {
        #pragma unroll
        for (int half = 0; half < 2; half++) {
            int row = rw + mt * 16 + (lane >> 2) + half * 8;
            if (row >= M) continue;
            #pragma unroll
            for (int nt = 0; nt < 4; nt++) {
                int col = cw + nt * 8 + (lane & 3) * 2;
                if (col >= N) continue;
                float v0 = acc[mt][nt][half * 2 + 0];
                float v1 = acc[mt][nt][half * 2 + 1];
                if (BIAS) { v0 += bias[col]; v1 += bias[col + 1]; }
                if (LEAKY) {
                    v0 = (v0 >= 0.f) ? v0 : NEG_SLOPE * v0;
                    v1 = (v1 >= 0.f) ? v1 : NEG_SLOPE * v1;
                }
                float2 o; o.x = v0; o.y = v1;
                *(float2*)(C + (size_t)row * ldc + col) = o;
            }
        }
    }
}

// ---------------- launch 4: GEMM1 + T1 reduce + imgb2 (merged) ---------------
__global__ void __launch_bounds__(256, 2) k_gemm1_fused(
    const float* __restrict__ A, const float* __restrict__ B,
    float* __restrict__ C, const float* __restrict__ bias,
    const float* __restrict__ img, const float* __restrict__ b2)
{
    extern __shared__ char smem[];
    if (blockIdx.x < G1_GRID) {
        int bx = blockIdx.x & 15;
        int by = blockIdx.x >> 4;
        gemm_core<true, true>(A, FTEXT, B, FTEXT, C, FHID, bias,
                              NNODES, FHID, FTEXT, bx, by, smem);
    } else if (blockIdx.x < G1_GRID + 256) {
        int idx = (blockIdx.x - G1_GRID) * 256 + threadIdx.x;
        float acc = 0.f;
        #pragma unroll
        for (int s = 0; s < NSPLIT; s++)
            acc += g_T1p[(size_t)s * (BBATCH * FHID) + idx];
        g_T1[idx] = acc;
    } else {
        int wid = threadIdx.x >> 5, lane = threadIdx.x & 31;
        for (int i = 0; i < 8; i++) {
            int b = wid * 8 + i;
            float acc = 0.f;
            for (int k = lane; k < FOUT; k += 32)
                acc += img[(size_t)b * FOUT + k] * b2[k];
            #pragma unroll
            for (int off = 16; off > 0; off >>= 1)
                acc += __shfl_down_sync(0xffffffffu, acc, off);
            if (lane == 0) g_imgb2[b] = acc;
        }
    }
}

// ---------------- launch 5: T2 = X1 @ T1^T, 64-row tiles, plain fp16 ---------
__global__ void __launch_bounds__(128, 4) k_t2(
    const float* __restrict__ A, const float* __restrict__ B,
    float* __restrict__ C)
{
    extern __shared__ char smem[];
    const int A64 = 64 * 80;
    const int B64 = 64 * 80;
    const int STAGE = A64 + B64;           // 10240
    const int M = NNODES, K = FHID;

    int tid = threadIdx.x;
    int wid = tid >> 5, lane = tid & 31;
    int wm = wid & 1, wn = wid >> 1;
    int row0 = blockIdx.x * 64;
    uint32_t smem_u = smem_to_u32(smem);

    float acc[2][4][4];
    #pragma unroll
    for (int mt = 0; mt < 2; mt++)
        #pragma unroll
        for (int nt = 0; nt < 4; nt++)
            #pragma unroll
            for (int q = 0; q < 4; q++) acc[mt][nt][q] = 0.f;

    float4 aR[4], bR[4];
    const int nT = K >> 5;

    auto LDG = [&](int t) {
        int kb = t * 32;
        #pragma unroll
        for (int i = 0; i < 4; i++) {
            int idx = tid + i * 128;
            int r = idx >> 3, kk = (idx & 7) * 4;
            int row = row0 + r; row = (row < M) ? row : (M - 1);
            aR[i] = *(const float4*)(A + (size_t)row * K + kb + kk);
            bR[i] = *(const float4*)(B + (size_t)r * K + kb + kk);
        }
    };
    auto STS = [&](int s) {
        char* base = smem + s * STAGE;
        #pragma unroll
        for (int i = 0; i < 4; i++) {
            int idx = tid + i * 128;
            int r = idx >> 3, kk = (idx & 7) * 4;
            *(uint2*)(base + r * 80 + kk * 2) = f4_h(aR[i]);
            *(uint2*)(base + A64 + r * 80 + kk * 2) = f4_h(bR[i]);
        }
    };
    auto COMPUTE = [&](int s) {
        uint32_t sb = smem_u + s * STAGE;
        uint32_t aH = sb + (uint32_t)((wm * 32 + (lane & 15)) * 80 + (lane >> 4) * 16);
        uint32_t bH = sb + A64 +
            (uint32_t)((wn * 32 + ((lane >> 4) & 1) * 8 + (lane & 7)) * 80 + ((lane >> 3) & 1) * 16);
        #pragma unroll
        for (int ks = 0; ks < 2; ks++) {
            uint32_t ah[2][4], bh[2][4];
            #pragma unroll
            for (int mt = 0; mt < 2; mt++)
                ldsm_x4(ah[mt], aH + mt * 16 * 80 + ks * 32);
            #pragma unroll
            for (int g = 0; g < 2; g++)
                ldsm_x4(bh[g], bH + g * 16 * 80 + ks * 32);
            #pragma unroll
            for (int mt = 0; mt < 2; mt++)
                #pragma unroll
                for (int nt = 0; nt < 4; nt++)
                    mma_f16(acc[mt][nt], ah[mt], &bh[nt >> 1][(nt & 1) * 2]);
        }
    };

    LDG(0);
    STS(0);
    LDG(1);
    __syncthreads();
    for (int t = 0; t < nT; t++) {
        COMPUTE(t & 1);
        if (t + 1 < nT) STS((t + 1) & 1);
        __syncthreads();
        if (t + 2 < nT) LDG(t + 2);
    }

    int rw = row0 + wm * 32;
    int cw = wn * 32;
    #pragma unroll
    for (int mt = 0; mt < 2; mt++) {
        #pragma unroll
        for (int half = 0; half < 2; half++) {
            int row = rw + mt * 16 + (lane >> 2) + half * 8;
            if (row >= M) continue;
            #pragma unroll
            for (int nt = 0; nt < 4; nt++) {
                int col = cw + nt * 8 + (lane & 3) * 2;
                float2 o;
                o.x = acc[mt][nt][half * 2 + 0];
                o.y = acc[mt][nt][half * 2 + 1];
                *(float2*)(C + (size_t)row * BBATCH + col) = o;
            }
        }
    }
}

// ---------------- launch 6: output agg (packed edges) + transpose ------------
__global__ void __launch_bounds__(256) k_aggOutT(float* __restrict__ out) {
    if (blockIdx.x >= 625) {
        int i = (blockIdx.x - 625) * 256 + threadIdx.x;
        if (i < NNODES) { g_deg[i] = 0.f; g_cnt[i] = 0; g_cursor[i] = 0; }
        return;
    }
    __shared__ float s[32][65];
    int n0 = blockIdx.x * 32;
    int tid = threadIdx.x;
    int slot = tid >> 5;
    int b2 = tid & 31;
    float bx = g_imgb2[2 * b2];
    float by = g_imgb2[2 * b2 + 1];
    #pragma unroll
    for (int rnd = 0; rnd < 4; rnd++) {
        int nl = rnd * 8 + slot;
        int n = n0 + nl;
        float ax = bx, ay = by;
        int st = g_rowptr[n], en = g_rowptr[n + 1];
        for (int e = st; e < en; e++) {
            int2 ed = g_edgeB[e];
            float w = __int_as_float(ed.y);
            float2 v = *(const float2*)(g_T2 + ed.x + 2 * b2);
            ax += w * v.x;
            ay += w * v.y;
        }
        s[nl][2 * b2]     = ax;
        s[nl][2 * b2 + 1] = ay;
    }
    __syncthreads();
    #pragma unroll
    for (int i = 0; i < 8; i++) {
        int idx = tid + i * 256;
        int bb = idx >> 5, nn = idx & 31;
        out[(size_t)bb * NNODES + n0 + nn] = s[nn][bb];
    }
}

// ---------------- launch ----------------
extern "C" void kernel_launch(void* const* d_in, const int* in_sizes, int n_in,
                              void* d_out, int out_size) {
    const float* img  = (const float*)d_in[0];
    const float* nf   = (const float*)d_in[1];
    const int*   esrc = (const int*)d_in[2];
    const int*   edst = (const int*)d_in[3];
    const float* ew   = (const float*)d_in[4];
    const float* W1   = (const float*)d_in[5];
    const float* b1   = (const float*)d_in[6];
    const float* W2   = (const float*)d_in[7];
    const float* b2   = (const float*)d_in[8];
    float* out = (float*)d_out;

    float *dY, *dX1, *dW1t, *dT1, *dT2;
    cudaGetSymbolAddress((void**)&dY,   g_Y);
    cudaGetSymbolAddress((void**)&dX1,  g_X1);
    cudaGetSymbolAddress((void**)&dW1t, g_W1t);
    cudaGetSymbolAddress((void**)&dT1,  g_T1);
    cudaGetSymbolAddress((void**)&dT2,  g_T2);

    const int SMEM1 = 30720;   // gemm_core: 2 stages x 15360
    const int SMEM2 = 20480;   // k_t2:      2 stages x 10240
    cudaFuncSetAttribute(k_gemm1_fused, cudaFuncAttributeMaxDynamicSharedMemorySize, SMEM1);
    cudaFuncSetAttribute(k_t2,          cudaFuncAttributeMaxDynamicSharedMemorySize, SMEM2);

    // 0: W1 transpose first, then degree atomics
    k_deg_w1t<<<320 + 625, 256>>>(edst, ew, W1);
    // 1: scan + dinv
    k_scandinv<<<1, 1024>>>();
    // 2: T1 split-K first, then CSR fill
    k_fill_t1<<<T1_BLKS + 625, 256>>>(esrc, edst, ew, img, W2);
    // 3: layer-1 aggregation (prefetched barrier-free gather)
    k_aggY<<<NNODES, 128>>>(nf);
    // 4: GEMM1 + T1 reduce + imgb2 (plain fp16 MMA)
    k_gemm1_fused<<<G1_GRID + 256 + 1, 256, SMEM1>>>(dY, dW1t, dX1, b1, img, b2);
    // 5: T2 (plain fp16 MMA, 64-row tiles)
    k_t2<<<(NNODES + 63) / 64, 128, SMEM2>>>(dX1, dT1, dT2);
    // 6: output aggregation (packed edges) + transpose + re-zero scratch
    k_aggOutT<<<625 + 79, 256>>>(out);
}